// round 7
// baseline (speedup 1.0000x reference)
#include <cuda_runtime.h>
#include <math.h>
#include <stdint.h>

#define N_NODES 100000
#define E_EDGES 400000
#define ND 128
#define ED 64
#define HD 128
#define LN_EPS 1e-5f

// Scratch (__device__ globals: allocation-free rule)
__device__ float g_hagg[(size_t)N_NODES * HD];
__device__ float g_deg[N_NODES];
__device__ float g_P[(size_t)N_NODES * HD];
__device__ float g_Q[(size_t)N_NODES * HD];
__device__ float g_R[(size_t)E_EDGES * HD];
__device__ float g_T[(size_t)N_NODES * HD];
__device__ float g_H[(size_t)N_NODES * HD];
__device__ float g_W2p[HD * HD];
__device__ float g_d2[HD];

// ---------------- helpers ----------------
__device__ __forceinline__ void red_add_v4(float* p, float a, float b, float c, float d) {
    asm volatile("red.global.add.v4.f32 [%0], {%1, %2, %3, %4};"
                 :: "l"(p), "f"(a), "f"(b), "f"(c), "f"(d) : "memory");
}
__device__ __forceinline__ void red_add_f32(float* p, float v) {
    asm volatile("red.global.add.f32 [%0], %1;" :: "l"(p), "f"(v) : "memory");
}
__device__ __forceinline__ float2 split_f(float x) {
    uint32_t hi;
    asm("cvt.rna.tf32.f32 %0, %1;" : "=r"(hi) : "f"(x));
    float h = __uint_as_float(hi);
    float r = x - h;
    uint32_t lo;
    asm("cvt.rna.tf32.f32 %0, %1;" : "=r"(lo) : "f"(r));
    return make_float2(h, __uint_as_float(lo));
}
__device__ __forceinline__ void mma_tf32(float d[4], const uint32_t a[4], const uint32_t b[2]) {
    asm("mma.sync.aligned.m16n8k8.row.col.f32.tf32.tf32.f32 "
        "{%0,%1,%2,%3}, {%4,%5,%6,%7}, {%8,%9}, {%0,%1,%2,%3};"
        : "+f"(d[0]), "+f"(d[1]), "+f"(d[2]), "+f"(d[3])
        : "r"(a[0]), "r"(a[1]), "r"(a[2]), "r"(a[3]), "r"(b[0]), "r"(b[1]));
}

__global__ void zero_kernel() {
    float4* p = reinterpret_cast<float4*>(g_hagg);
    const int n4 = N_NODES * HD / 4;
    for (int i = blockIdx.x * blockDim.x + threadIdx.x; i < n4;
         i += gridDim.x * blockDim.x)
        p[i] = make_float4(0.f, 0.f, 0.f, 0.f);
    for (int i = blockIdx.x * blockDim.x + threadIdx.x; i < N_NODES;
         i += gridDim.x * blockDim.x)
        g_deg[i] = 0.f;
}

__global__ void d2_kernel(const float* __restrict__ uw1, const float* __restrict__ b2) {
    int j = threadIdx.x;
    float s = 0.f;
    for (int k = 0; k < HD; k++)
        s = fmaf(b2[k], uw1[(ND + k) * HD + j], s);
    g_d2[j] = s;
}

// ---------------------------------------------------------------------------
// gemm_tc: C[M][128] = A[M][K] @ W[K][128] (+bias)(+C if addC)(+resid).
// 3xTF32 mma.sync; split-at-STS (hi/lo SMEM planes); register-prefetch
// double buffering. BM=64/BN=128/BK=16; 8 warps (2x4), warp tile 32x32.
// ---------------------------------------------------------------------------
__global__ __launch_bounds__(256, 2) void gemm_tc(
    const float* __restrict__ A, int M, int K,
    const float* __restrict__ W, const float* __restrict__ bias,
    const float* __restrict__ resid, int addC, float* __restrict__ C)
{
    __shared__ float Ahi[64][20], Alo[64][20];
    __shared__ float Whi[16][136], Wlo[16][136];

    const int tid = threadIdx.x;
    const int lane = tid & 31, warp = tid >> 5;
    const int wm = warp >> 2, wn = warp & 3;   // 2 x 4 warp grid
    const int g = lane >> 2, tig = lane & 3;
    const long rBase = (long)blockIdx.x * 64;

    const int arow = tid >> 2, akq = tid & 3;  // A loader: 64 rows x 4 quads
    long gArow = rBase + arow; if (gArow >= M) gArow = M - 1;
    const int wkr = tid >> 5, wcc = tid & 31;  // W loader

    const int nChunks = K >> 4;

    float d[2][4][4];
    #pragma unroll
    for (int mf = 0; mf < 2; mf++)
        #pragma unroll
        for (int nf = 0; nf < 4; nf++)
            #pragma unroll
            for (int q = 0; q < 4; q++) d[mf][nf][q] = 0.f;

    // prefetch chunk 0 into registers
    float4 xa  = *(const float4*)(A + gArow * K + akq * 4);
    float4 xw0 = *(const float4*)(W + (long)wkr * 128 + wcc * 4);
    float4 xw1 = *(const float4*)(W + (long)(wkr + 8) * 128 + wcc * 4);

    for (int c = 0; c < nChunks; c++) {
        __syncthreads();   // previous chunk's compute done
        {
            const float* xp = (const float*)&xa;
            #pragma unroll
            for (int q = 0; q < 4; q++) {
                float2 s = split_f(xp[q]);
                Ahi[arow][akq * 4 + q] = s.x;
                Alo[arow][akq * 4 + q] = s.y;
            }
            const float* wp0 = (const float*)&xw0;
            const float* wp1 = (const float*)&xw1;
            #pragma unroll
            for (int q = 0; q < 4; q++) {
                float2 s0 = split_f(wp0[q]);
                Whi[wkr][wcc * 4 + q] = s0.x;
                Wlo[wkr][wcc * 4 + q] = s0.y;
                float2 s1 = split_f(wp1[q]);
                Whi[wkr + 8][wcc * 4 + q] = s1.x;
                Wlo[wkr + 8][wcc * 4 + q] = s1.y;
            }
        }
        __syncthreads();
        if (c + 1 < nChunks) {   // prefetch next chunk (overlaps compute)
            int kc = (c + 1) * 16;
            xa  = *(const float4*)(A + gArow * K + kc + akq * 4);
            xw0 = *(const float4*)(W + (long)(kc + wkr) * 128 + wcc * 4);
            xw1 = *(const float4*)(W + (long)(kc + 8 + wkr) * 128 + wcc * 4);
        }
        #pragma unroll
        for (int k8 = 0; k8 < 16; k8 += 8) {
            uint32_t ahi[2][4], alo[2][4], bhi[4][2], blo[4][2];
            #pragma unroll
            for (int mf = 0; mf < 2; mf++) {
                int mb = wm * 32 + mf * 16;
                ahi[mf][0] = __float_as_uint(Ahi[mb + g][k8 + tig]);
                ahi[mf][1] = __float_as_uint(Ahi[mb + 8 + g][k8 + tig]);
                ahi[mf][2] = __float_as_uint(Ahi[mb + g][k8 + tig + 4]);
                ahi[mf][3] = __float_as_uint(Ahi[mb + 8 + g][k8 + tig + 4]);
                alo[mf][0] = __float_as_uint(Alo[mb + g][k8 + tig]);
                alo[mf][1] = __float_as_uint(Alo[mb + 8 + g][k8 + tig]);
                alo[mf][2] = __float_as_uint(Alo[mb + g][k8 + tig + 4]);
                alo[mf][3] = __float_as_uint(Alo[mb + 8 + g][k8 + tig + 4]);
            }
            #pragma unroll
            for (int nf = 0; nf < 4; nf++) {
                int nb = wn * 32 + nf * 8;
                bhi[nf][0] = __float_as_uint(Whi[k8 + tig][nb + g]);
                bhi[nf][1] = __float_as_uint(Whi[k8 + tig + 4][nb + g]);
                blo[nf][0] = __float_as_uint(Wlo[k8 + tig][nb + g]);
                blo[nf][1] = __float_as_uint(Wlo[k8 + tig + 4][nb + g]);
            }
            #pragma unroll
            for (int mf = 0; mf < 2; mf++)
                #pragma unroll
                for (int nf = 0; nf < 4; nf++) {
                    mma_tf32(d[mf][nf], ahi[mf], bhi[nf]);
                    mma_tf32(d[mf][nf], alo[mf], bhi[nf]);
                    mma_tf32(d[mf][nf], ahi[mf], blo[nf]);
                }
        }
    }

    // epilogue
    #pragma unroll
    for (int mf = 0; mf < 2; mf++) {
        #pragma unroll
        for (int r2 = 0; r2 < 2; r2++) {
            long m = rBase + wm * 32 + mf * 16 + g + r2 * 8;
            if (m < M) {
                #pragma unroll
                for (int nf = 0; nf < 4; nf++) {
                    int n = wn * 32 + nf * 8 + 2 * tig;
                    float v0 = d[mf][nf][r2 * 2];
                    float v1 = d[mf][nf][r2 * 2 + 1];
                    if (bias)  { v0 += bias[n];  v1 += bias[n + 1]; }
                    if (addC)  { float2 cc = *(const float2*)(C + m * 128 + n);
                                 v0 += cc.x; v1 += cc.y; }
                    if (resid) { float2 rr = *(const float2*)(resid + m * 128 + n);
                                 v0 += rr.x; v1 += rr.y; }
                    *(float2*)(C + m * 128 + n) = make_float2(v0, v1);
                }
            }
        }
    }
}

// ---------------------------------------------------------------------------
// Edge kernel: one warp per UNDIRECTED edge; both directions.
// ---------------------------------------------------------------------------
__global__ __launch_bounds__(256) void edge_kernel(
    const int* __restrict__ eidx,
    const float* __restrict__ g1, const float* __restrict__ be1)
{
    const int wid = threadIdx.x >> 5, lane = threadIdx.x & 31;
    const long e = (long)blockIdx.x * 8 + wid;
    const int s = eidx[e], t = eidx[E_EDGES + e];

    float4 ps = *(const float4*)(g_P + (long)s * HD + lane * 4);
    float4 pt = *(const float4*)(g_P + (long)t * HD + lane * 4);
    float4 qs = *(const float4*)(g_Q + (long)s * HD + lane * 4);
    float4 qt = *(const float4*)(g_Q + (long)t * HD + lane * 4);
    float4 r  = *(const float4*)(g_R + e * HD + lane * 4);
    float4 gg = *(const float4*)&g1[lane * 4];
    float4 bb = *(const float4*)&be1[lane * 4];

    float4 vf = make_float4(ps.x + qt.x + r.x, ps.y + qt.y + r.y,
                            ps.z + qt.z + r.z, ps.w + qt.w + r.w);
    float4 vb = make_float4(pt.x + qs.x + r.x, pt.y + qs.y + r.y,
                            pt.z + qs.z + r.z, pt.w + qs.w + r.w);

    float s1f = vf.x + vf.y + vf.z + vf.w;
    float ssf = vf.x * vf.x + vf.y * vf.y + vf.z * vf.z + vf.w * vf.w;
    float s1b = vb.x + vb.y + vb.z + vb.w;
    float ssb = vb.x * vb.x + vb.y * vb.y + vb.z * vb.z + vb.w * vb.w;
    #pragma unroll
    for (int o = 16; o >= 1; o >>= 1) {
        s1f += __shfl_xor_sync(0xffffffffu, s1f, o);
        ssf += __shfl_xor_sync(0xffffffffu, ssf, o);
        s1b += __shfl_xor_sync(0xffffffffu, s1b, o);
        ssb += __shfl_xor_sync(0xffffffffu, ssb, o);
    }
    {
        float mean = s1f * (1.0f / HD);
        float var  = ssf * (1.0f / HD) - mean * mean;
        float rstd = rsqrtf(var + LN_EPS);
        float h0 = fmaxf((vf.x - mean) * rstd * gg.x + bb.x, 0.f);
        float h1 = fmaxf((vf.y - mean) * rstd * gg.y + bb.y, 0.f);
        float h2 = fmaxf((vf.z - mean) * rstd * gg.z + bb.z, 0.f);
        float h3 = fmaxf((vf.w - mean) * rstd * gg.w + bb.w, 0.f);
        red_add_v4(g_hagg + (long)t * HD + lane * 4, h0, h1, h2, h3);
    }
    {
        float mean = s1b * (1.0f / HD);
        float var  = ssb * (1.0f / HD) - mean * mean;
        float rstd = rsqrtf(var + LN_EPS);
        float h0 = fmaxf((vb.x - mean) * rstd * gg.x + bb.x, 0.f);
        float h1 = fmaxf((vb.y - mean) * rstd * gg.y + bb.y, 0.f);
        float h2 = fmaxf((vb.z - mean) * rstd * gg.z + bb.z, 0.f);
        float h3 = fmaxf((vb.w - mean) * rstd * gg.w + bb.w, 0.f);
        red_add_v4(g_hagg + (long)s * HD + lane * 4, h0, h1, h2, h3);
    }
    if (lane == 0) { red_add_f32(g_deg + t, 1.0f); red_add_f32(g_deg + s, 1.0f); }
}

// ---------------------------------------------------------------------------
// ln2: g_H = relu(LN(g_T + deg*d2) * g2 + be2).  One warp per node row.
// ---------------------------------------------------------------------------
__global__ __launch_bounds__(256) void ln2_kernel(
    const float* __restrict__ g2, const float* __restrict__ be2)
{
    const int row = blockIdx.x * 8 + (threadIdx.x >> 5);
    const int lane = threadIdx.x & 31;
    if (row >= N_NODES) return;
    float4 v = *(const float4*)(g_T + (long)row * HD + lane * 4);
    float dg = g_deg[row];
    float4 dd = *(const float4*)&g_d2[lane * 4];
    v.x += dg * dd.x; v.y += dg * dd.y; v.z += dg * dd.z; v.w += dg * dd.w;
    float s1 = v.x + v.y + v.z + v.w;
    float ss = v.x * v.x + v.y * v.y + v.z * v.z + v.w * v.w;
    #pragma unroll
    for (int o = 16; o >= 1; o >>= 1) {
        s1 += __shfl_xor_sync(0xffffffffu, s1, o);
        ss += __shfl_xor_sync(0xffffffffu, ss, o);
    }
    float mean = s1 * (1.0f / HD);
    float var  = ss * (1.0f / HD) - mean * mean;
    float rstd = rsqrtf(var + LN_EPS);
    float4 gg = *(const float4*)&g2[lane * 4];
    float4 bb = *(const float4*)&be2[lane * 4];
    float4 h;
    h.x = fmaxf((v.x - mean) * rstd * gg.x + bb.x, 0.f);
    h.y = fmaxf((v.y - mean) * rstd * gg.y + bb.y, 0.f);
    h.z = fmaxf((v.z - mean) * rstd * gg.z + bb.z, 0.f);
    h.w = fmaxf((v.w - mean) * rstd * gg.w + bb.w, 0.f);
    *(float4*)(g_H + (long)row * HD + lane * 4) = h;
}

extern "C" void kernel_launch(void* const* d_in, const int* in_sizes, int n_in,
                              void* d_out, int out_size)
{
    const float* nf   = (const float*)d_in[0];
    const float* ef   = (const float*)d_in[1];
    const int*   eidx = (const int*)  d_in[2];
    const float* w1   = (const float*)d_in[3];
    const float* b1   = (const float*)d_in[4];
    const float* g1   = (const float*)d_in[5];
    const float* be1  = (const float*)d_in[6];
    const float* w2   = (const float*)d_in[7];
    const float* b2   = (const float*)d_in[8];
    const float* uw1  = (const float*)d_in[9];
    const float* ub1  = (const float*)d_in[10];
    const float* g2   = (const float*)d_in[11];
    const float* be2  = (const float*)d_in[12];
    const float* uw2  = (const float*)d_in[13];
    const float* ub2  = (const float*)d_in[14];
    float* out = (float*)d_out;

    float *dP, *dQ, *dR, *dT, *dH, *dW2p, *dHagg;
    cudaGetSymbolAddress((void**)&dP,    g_P);
    cudaGetSymbolAddress((void**)&dQ,    g_Q);
    cudaGetSymbolAddress((void**)&dR,    g_R);
    cudaGetSymbolAddress((void**)&dT,    g_T);
    cudaGetSymbolAddress((void**)&dH,    g_H);
    cudaGetSymbolAddress((void**)&dW2p,  g_W2p);
    cudaGetSymbolAddress((void**)&dHagg, g_hagg);

    const int gN = (N_NODES + 63) / 64;   // 1563
    const int gE = (E_EDGES + 63) / 64;   // 6250

    zero_kernel<<<592, 256>>>();
    d2_kernel<<<1, 128>>>(uw1, b2);
    // W2p = W2 @ uw1b
    gemm_tc<<<2, 256>>>(w2, 128, HD, uw1 + ND * HD, nullptr, nullptr, 0, dW2p);
    // P = nf@W1a, Q = nf@W1b, R = ef@W1c + b1
    gemm_tc<<<gN, 256>>>(nf, N_NODES, ND, w1, nullptr, nullptr, 0, dP);
    gemm_tc<<<gN, 256>>>(nf, N_NODES, ND, w1 + ND * HD, nullptr, nullptr, 0, dQ);
    gemm_tc<<<gE, 256>>>(ef, E_EDGES, ED, w1 + 2 * ND * HD, b1, nullptr, 0, dR);
    // edges: gather + LN + scatter
    edge_kernel<<<E_EDGES / 8, 256>>>(eidx, g1, be1);
    // update MLP: T = nf@uw1a + ub1; T += hagg@W2p; H = relu(LN(T + deg*d2))
    gemm_tc<<<gN, 256>>>(nf, N_NODES, ND, uw1, ub1, nullptr, 0, dT);
    gemm_tc<<<gN, 256>>>(dHagg, N_NODES, HD, dW2p, nullptr, nullptr, 1, dT);
    ln2_kernel<<<(N_NODES + 7) / 8, 256>>>(g2, be2);
    // out = H@uw2 + ub2 + nf
    gemm_tc<<<gN, 256>>>(dH, N_NODES, HD, uw2, ub2, nf, 0, out);
}

// round 8
// speedup vs baseline: 1.2412x; 1.2412x over previous
#include <cuda_runtime.h>
#include <math.h>
#include <stdint.h>

#define N_NODES 100000
#define E_EDGES 400000
#define ND 128
#define ED 64
#define HD 128
#define LN_EPS 1e-5f

// Scratch (__device__ globals: allocation-free rule)
__device__ float g_hagg[(size_t)N_NODES * HD];
__device__ float g_deg[N_NODES];
__device__ float g_P[(size_t)N_NODES * HD];
__device__ float g_Q[(size_t)N_NODES * HD];
__device__ float g_R[(size_t)E_EDGES * HD];
__device__ float g_T[(size_t)N_NODES * HD];
__device__ float g_H[(size_t)N_NODES * HD];
__device__ float g_W2p[HD * HD];
__device__ float g_d2[HD];

// Pre-split weight planes (hi/lo TF32). Layout offsets:
//   w1  @ 0       (320*128 = 40960)
//   uw1 @ 40960   (256*128 = 32768)   [uw1b rows start at 40960+16384=57344]
//   uw2 @ 73728   (128*128 = 16384)
//   w2  @ 90112   (128*128 = 16384)
//   W2p @ 106496  (128*128 = 16384)
#define OFF_W1   0
#define OFF_UW1  40960
#define OFF_UW1B 57344
#define OFF_UW2  73728
#define OFF_W2   90112
#define OFF_W2P  106496
__device__ float g_Whi[122880];
__device__ float g_Wlo[122880];

// ---------------- helpers ----------------
__device__ __forceinline__ void red_add_v4(float* p, float a, float b, float c, float d) {
    asm volatile("red.global.add.v4.f32 [%0], {%1, %2, %3, %4};"
                 :: "l"(p), "f"(a), "f"(b), "f"(c), "f"(d) : "memory");
}
__device__ __forceinline__ void red_add_f32(float* p, float v) {
    asm volatile("red.global.add.f32 [%0], %1;" :: "l"(p), "f"(v) : "memory");
}
__device__ __forceinline__ float2 split_f(float x) {
    uint32_t hi;
    asm("cvt.rna.tf32.f32 %0, %1;" : "=r"(hi) : "f"(x));
    float h = __uint_as_float(hi);
    float r = x - h;
    uint32_t lo;
    asm("cvt.rna.tf32.f32 %0, %1;" : "=r"(lo) : "f"(r));
    return make_float2(h, __uint_as_float(lo));
}
__device__ __forceinline__ void mma_tf32(float d[4], const uint32_t a[4], const uint32_t b[2]) {
    asm("mma.sync.aligned.m16n8k8.row.col.f32.tf32.tf32.f32 "
        "{%0,%1,%2,%3}, {%4,%5,%6,%7}, {%8,%9}, {%0,%1,%2,%3};"
        : "+f"(d[0]), "+f"(d[1]), "+f"(d[2]), "+f"(d[3])
        : "r"(a[0]), "r"(a[1]), "r"(a[2]), "r"(a[3]), "r"(b[0]), "r"(b[1]));
}
__device__ __forceinline__ void cp_async16(void* smem, const void* gmem) {
    uint32_t s = (uint32_t)__cvta_generic_to_shared(smem);
    asm volatile("cp.async.cg.shared.global [%0], [%1], 16;" :: "r"(s), "l"(gmem));
}
#define CP_COMMIT() asm volatile("cp.async.commit_group;")
#define CP_WAIT1()  asm volatile("cp.async.wait_group 1;")

__global__ void zero_kernel() {
    float4* p = reinterpret_cast<float4*>(g_hagg);
    const int n4 = N_NODES * HD / 4;
    for (int i = blockIdx.x * blockDim.x + threadIdx.x; i < n4;
         i += gridDim.x * blockDim.x)
        p[i] = make_float4(0.f, 0.f, 0.f, 0.f);
    for (int i = blockIdx.x * blockDim.x + threadIdx.x; i < N_NODES;
         i += gridDim.x * blockDim.x)
        g_deg[i] = 0.f;
}

__global__ void split_kernel(const float* __restrict__ src, int n, int off) {
    int i = blockIdx.x * blockDim.x + threadIdx.x;
    if (i < n) {
        float2 s = split_f(src[i]);
        g_Whi[off + i] = s.x;
        g_Wlo[off + i] = s.y;
    }
}

__global__ void d2_kernel(const float* __restrict__ uw1, const float* __restrict__ b2) {
    int j = threadIdx.x;
    float s = 0.f;
    for (int k = 0; k < HD; k++)
        s = fmaf(b2[k], uw1[(ND + k) * HD + j], s);
    g_d2[j] = s;
}

// ---------------------------------------------------------------------------
// gemm_tc: C[M][128] = A[M][K] @ W[K][128] (+bias)(+C if addC)(+resid).
// W supplied as pre-split hi/lo TF32 planes (g_Whi/g_Wlo + offset).
// 3xTF32 mma.sync; A raw in SMEM (split at fragment load); cp.async
// double-buffered. BM=64/BN=128/BK=16; 8 warps (2x4), warp tile 32x32.
// ---------------------------------------------------------------------------
__global__ __launch_bounds__(256, 2) void gemm_tc(
    const float* __restrict__ A, int M, int K,
    int wOff, const float* __restrict__ bias,
    const float* __restrict__ resid, int addC, float* __restrict__ C)
{
    __shared__ float As[2][64][20];
    __shared__ float Whs[2][16][136];
    __shared__ float Wls[2][16][136];

    const float* Whi = g_Whi + wOff;
    const float* Wlo = g_Wlo + wOff;

    const int tid = threadIdx.x;
    const int lane = tid & 31, warp = tid >> 5;
    const int wm = warp >> 2, wn = warp & 3;   // 2 x 4 warp grid
    const int g = lane >> 2, tig = lane & 3;
    const long rBase = (long)blockIdx.x * 64;

    const int arow = tid >> 2, akq = tid & 3;  // A loader: 64 rows x 4 quads
    long gArow = rBase + arow; if (gArow >= M) gArow = M - 1;
    const int wkr = tid >> 5, wcc = tid & 31;  // W loader

    const int nChunks = K >> 4;

    float d[2][4][4];
    #pragma unroll
    for (int mf = 0; mf < 2; mf++)
        #pragma unroll
        for (int nf = 0; nf < 4; nf++)
            #pragma unroll
            for (int q = 0; q < 4; q++) d[mf][nf][q] = 0.f;

    // prologue: chunk 0
    cp_async16(&As[0][arow][akq * 4], A + gArow * K + akq * 4);
    cp_async16(&Whs[0][wkr][wcc * 4],     Whi + (long)wkr * 128 + wcc * 4);
    cp_async16(&Whs[0][wkr + 8][wcc * 4], Whi + (long)(wkr + 8) * 128 + wcc * 4);
    cp_async16(&Wls[0][wkr][wcc * 4],     Wlo + (long)wkr * 128 + wcc * 4);
    cp_async16(&Wls[0][wkr + 8][wcc * 4], Wlo + (long)(wkr + 8) * 128 + wcc * 4);
    CP_COMMIT();

    for (int c = 0; c < nChunks; c++) {
        if (c + 1 < nChunks) {
            int kc = (c + 1) * 16, buf = (c + 1) & 1;
            cp_async16(&As[buf][arow][akq * 4], A + gArow * K + kc + akq * 4);
            cp_async16(&Whs[buf][wkr][wcc * 4],     Whi + (long)(kc + wkr) * 128 + wcc * 4);
            cp_async16(&Whs[buf][wkr + 8][wcc * 4], Whi + (long)(kc + 8 + wkr) * 128 + wcc * 4);
            cp_async16(&Wls[buf][wkr][wcc * 4],     Wlo + (long)(kc + wkr) * 128 + wcc * 4);
            cp_async16(&Wls[buf][wkr + 8][wcc * 4], Wlo + (long)(kc + 8 + wkr) * 128 + wcc * 4);
        }
        CP_COMMIT();
        CP_WAIT1();
        __syncthreads();
        const int buf = c & 1;
        #pragma unroll
        for (int k8 = 0; k8 < 16; k8 += 8) {
            uint32_t ahi[2][4], alo[2][4], bhi[4][2], blo[4][2];
            #pragma unroll
            for (int mf = 0; mf < 2; mf++) {
                int mb = wm * 32 + mf * 16;
                float a0 = As[buf][mb + g][k8 + tig];
                float a1 = As[buf][mb + 8 + g][k8 + tig];
                float a2 = As[buf][mb + g][k8 + tig + 4];
                float a3 = As[buf][mb + 8 + g][k8 + tig + 4];
                float2 s0 = split_f(a0), s1 = split_f(a1);
                float2 s2 = split_f(a2), s3 = split_f(a3);
                ahi[mf][0] = __float_as_uint(s0.x); alo[mf][0] = __float_as_uint(s0.y);
                ahi[mf][1] = __float_as_uint(s1.x); alo[mf][1] = __float_as_uint(s1.y);
                ahi[mf][2] = __float_as_uint(s2.x); alo[mf][2] = __float_as_uint(s2.y);
                ahi[mf][3] = __float_as_uint(s3.x); alo[mf][3] = __float_as_uint(s3.y);
            }
            #pragma unroll
            for (int nf = 0; nf < 4; nf++) {
                int nb = wn * 32 + nf * 8;
                bhi[nf][0] = __float_as_uint(Whs[buf][k8 + tig][nb + g]);
                bhi[nf][1] = __float_as_uint(Whs[buf][k8 + tig + 4][nb + g]);
                blo[nf][0] = __float_as_uint(Wls[buf][k8 + tig][nb + g]);
                blo[nf][1] = __float_as_uint(Wls[buf][k8 + tig + 4][nb + g]);
            }
            #pragma unroll
            for (int mf = 0; mf < 2; mf++)
                #pragma unroll
                for (int nf = 0; nf < 4; nf++) {
                    mma_tf32(d[mf][nf], ahi[mf], bhi[nf]);
                    mma_tf32(d[mf][nf], alo[mf], bhi[nf]);
                    mma_tf32(d[mf][nf], ahi[mf], blo[nf]);
                }
        }
        __syncthreads();   // all reads of buf done before it is refilled
    }

    // epilogue
    #pragma unroll
    for (int mf = 0; mf < 2; mf++) {
        #pragma unroll
        for (int r2 = 0; r2 < 2; r2++) {
            long m = rBase + wm * 32 + mf * 16 + g + r2 * 8;
            if (m < M) {
                #pragma unroll
                for (int nf = 0; nf < 4; nf++) {
                    int n = wn * 32 + nf * 8 + 2 * tig;
                    float v0 = d[mf][nf][r2 * 2];
                    float v1 = d[mf][nf][r2 * 2 + 1];
                    if (bias)  { v0 += bias[n];  v1 += bias[n + 1]; }
                    if (addC)  { float2 cc = *(const float2*)(C + m * 128 + n);
                                 v0 += cc.x; v1 += cc.y; }
                    if (resid) { float2 rr = *(const float2*)(resid + m * 128 + n);
                                 v0 += rr.x; v1 += rr.y; }
                    *(float2*)(C + m * 128 + n) = make_float2(v0, v1);
                }
            }
        }
    }
}

// ---------------------------------------------------------------------------
// Edge kernel: one warp per UNDIRECTED edge; both directions.
// ---------------------------------------------------------------------------
__global__ __launch_bounds__(256) void edge_kernel(
    const int* __restrict__ eidx,
    const float* __restrict__ g1, const float* __restrict__ be1)
{
    const int wid = threadIdx.x >> 5, lane = threadIdx.x & 31;
    const long e = (long)blockIdx.x * 8 + wid;
    const int s = eidx[e], t = eidx[E_EDGES + e];

    float4 ps = *(const float4*)(g_P + (long)s * HD + lane * 4);
    float4 pt = *(const float4*)(g_P + (long)t * HD + lane * 4);
    float4 qs = *(const float4*)(g_Q + (long)s * HD + lane * 4);
    float4 qt = *(const float4*)(g_Q + (long)t * HD + lane * 4);
    float4 r  = *(const float4*)(g_R + e * HD + lane * 4);
    float4 gg = *(const float4*)&g1[lane * 4];
    float4 bb = *(const float4*)&be1[lane * 4];

    float4 vf = make_float4(ps.x + qt.x + r.x, ps.y + qt.y + r.y,
                            ps.z + qt.z + r.z, ps.w + qt.w + r.w);
    float4 vb = make_float4(pt.x + qs.x + r.x, pt.y + qs.y + r.y,
                            pt.z + qs.z + r.z, pt.w + qs.w + r.w);

    float s1f = vf.x + vf.y + vf.z + vf.w;
    float ssf = vf.x * vf.x + vf.y * vf.y + vf.z * vf.z + vf.w * vf.w;
    float s1b = vb.x + vb.y + vb.z + vb.w;
    float ssb = vb.x * vb.x + vb.y * vb.y + vb.z * vb.z + vb.w * vb.w;
    #pragma unroll
    for (int o = 16; o >= 1; o >>= 1) {
        s1f += __shfl_xor_sync(0xffffffffu, s1f, o);
        ssf += __shfl_xor_sync(0xffffffffu, ssf, o);
        s1b += __shfl_xor_sync(0xffffffffu, s1b, o);
        ssb += __shfl_xor_sync(0xffffffffu, ssb, o);
    }
    {
        float mean = s1f * (1.0f / HD);
        float var  = ssf * (1.0f / HD) - mean * mean;
        float rstd = rsqrtf(var + LN_EPS);
        float h0 = fmaxf((vf.x - mean) * rstd * gg.x + bb.x, 0.f);
        float h1 = fmaxf((vf.y - mean) * rstd * gg.y + bb.y, 0.f);
        float h2 = fmaxf((vf.z - mean) * rstd * gg.z + bb.z, 0.f);
        float h3 = fmaxf((vf.w - mean) * rstd * gg.w + bb.w, 0.f);
        red_add_v4(g_hagg + (long)t * HD + lane * 4, h0, h1, h2, h3);
    }
    {
        float mean = s1b * (1.0f / HD);
        float var  = ssb * (1.0f / HD) - mean * mean;
        float rstd = rsqrtf(var + LN_EPS);
        float h0 = fmaxf((vb.x - mean) * rstd * gg.x + bb.x, 0.f);
        float h1 = fmaxf((vb.y - mean) * rstd * gg.y + bb.y, 0.f);
        float h2 = fmaxf((vb.z - mean) * rstd * gg.z + bb.z, 0.f);
        float h3 = fmaxf((vb.w - mean) * rstd * gg.w + bb.w, 0.f);
        red_add_v4(g_hagg + (long)s * HD + lane * 4, h0, h1, h2, h3);
    }
    if (lane == 0) { red_add_f32(g_deg + t, 1.0f); red_add_f32(g_deg + s, 1.0f); }
}

// ---------------------------------------------------------------------------
// ln2: g_H = relu(LN(g_T + deg*d2) * g2 + be2).  One warp per node row.
// ---------------------------------------------------------------------------
__global__ __launch_bounds__(256) void ln2_kernel(
    const float* __restrict__ g2, const float* __restrict__ be2)
{
    const int row = blockIdx.x * 8 + (threadIdx.x >> 5);
    const int lane = threadIdx.x & 31;
    if (row >= N_NODES) return;
    float4 v = *(const float4*)(g_T + (long)row * HD + lane * 4);
    float dg = g_deg[row];
    float4 dd = *(const float4*)&g_d2[lane * 4];
    v.x += dg * dd.x; v.y += dg * dd.y; v.z += dg * dd.z; v.w += dg * dd.w;
    float s1 = v.x + v.y + v.z + v.w;
    float ss = v.x * v.x + v.y * v.y + v.z * v.z + v.w * v.w;
    #pragma unroll
    for (int o = 16; o >= 1; o >>= 1) {
        s1 += __shfl_xor_sync(0xffffffffu, s1, o);
        ss += __shfl_xor_sync(0xffffffffu, ss, o);
    }
    float mean = s1 * (1.0f / HD);
    float var  = ss * (1.0f / HD) - mean * mean;
    float rstd = rsqrtf(var + LN_EPS);
    float4 gg = *(const float4*)&g2[lane * 4];
    float4 bb = *(const float4*)&be2[lane * 4];
    float4 h;
    h.x = fmaxf((v.x - mean) * rstd * gg.x + bb.x, 0.f);
    h.y = fmaxf((v.y - mean) * rstd * gg.y + bb.y, 0.f);
    h.z = fmaxf((v.z - mean) * rstd * gg.z + bb.z, 0.f);
    h.w = fmaxf((v.w - mean) * rstd * gg.w + bb.w, 0.f);
    *(float4*)(g_H + (long)row * HD + lane * 4) = h;
}

extern "C" void kernel_launch(void* const* d_in, const int* in_sizes, int n_in,
                              void* d_out, int out_size)
{
    const float* nf   = (const float*)d_in[0];
    const float* ef   = (const float*)d_in[1];
    const int*   eidx = (const int*)  d_in[2];
    const float* w1   = (const float*)d_in[3];
    const float* b1   = (const float*)d_in[4];
    const float* g1   = (const float*)d_in[5];
    const float* be1  = (const float*)d_in[6];
    const float* w2   = (const float*)d_in[7];
    const float* b2   = (const float*)d_in[8];
    const float* uw1  = (const float*)d_in[9];
    const float* ub1  = (const float*)d_in[10];
    const float* g2   = (const float*)d_in[11];
    const float* be2  = (const float*)d_in[12];
    const float* uw2  = (const float*)d_in[13];
    const float* ub2  = (const float*)d_in[14];
    float* out = (float*)d_out;

    float *dP, *dQ, *dR, *dT, *dH, *dW2p, *dHagg;
    cudaGetSymbolAddress((void**)&dP,    g_P);
    cudaGetSymbolAddress((void**)&dQ,    g_Q);
    cudaGetSymbolAddress((void**)&dR,    g_R);
    cudaGetSymbolAddress((void**)&dT,    g_T);
    cudaGetSymbolAddress((void**)&dH,    g_H);
    cudaGetSymbolAddress((void**)&dW2p,  g_W2p);
    cudaGetSymbolAddress((void**)&dHagg, g_hagg);

    const int gN = (N_NODES + 63) / 64;   // 1563
    const int gE = (E_EDGES + 63) / 64;   // 6250

    zero_kernel<<<592, 256>>>();
    d2_kernel<<<1, 128>>>(uw1, b2);
    // split all input weights into hi/lo TF32 planes
    split_kernel<<<(320 * 128 + 255) / 256, 256>>>(w1,  320 * 128, OFF_W1);
    split_kernel<<<(256 * 128 + 255) / 256, 256>>>(uw1, 256 * 128, OFF_UW1);
    split_kernel<<<(128 * 128 + 255) / 256, 256>>>(uw2, 128 * 128, OFF_UW2);
    split_kernel<<<(128 * 128 + 255) / 256, 256>>>(w2,  128 * 128, OFF_W2);
    // W2p = W2 @ uw1b, then split it
    gemm_tc<<<2, 256>>>(w2, 128, HD, OFF_UW1B, nullptr, nullptr, 0, dW2p);
    split_kernel<<<(128 * 128 + 255) / 256, 256>>>(dW2p, 128 * 128, OFF_W2P);
    // P = nf@W1a, Q = nf@W1b, R = ef@W1c + b1
    gemm_tc<<<gN, 256>>>(nf, N_NODES, ND, OFF_W1, nullptr, nullptr, 0, dP);
    gemm_tc<<<gN, 256>>>(nf, N_NODES, ND, OFF_W1 + ND * HD, nullptr, nullptr, 0, dQ);
    gemm_tc<<<gE, 256>>>(ef, E_EDGES, ED, OFF_W1 + 2 * ND * HD, b1, nullptr, 0, dR);
    // edges: gather + LN + scatter
    edge_kernel<<<E_EDGES / 8, 256>>>(eidx, g1, be1);
    // update MLP: T = nf@uw1a + ub1; T += hagg@W2p; H = relu(LN(T + deg*d2))
    gemm_tc<<<gN, 256>>>(nf, N_NODES, ND, OFF_UW1, ub1, nullptr, 0, dT);
    gemm_tc<<<gN, 256>>>(dHagg, N_NODES, HD, OFF_W2P, nullptr, nullptr, 1, dT);
    ln2_kernel<<<(N_NODES + 7) / 8, 256>>>(g2, be2);
    // out = H@uw2 + ub2 + nf
    gemm_tc<<<gN, 256>>>(dH, N_NODES, HD, OFF_UW2, ub2, nf, 0, out);
}

// round 9
// speedup vs baseline: 1.2928x; 1.0416x over previous
#include <cuda_runtime.h>
#include <math.h>
#include <stdint.h>

#define N_NODES 100000
#define E_EDGES 400000
#define ND 128
#define ED 64
#define HD 128
#define LN_EPS 1e-5f

// Scratch (__device__ globals: allocation-free rule)
__device__ float g_hagg[(size_t)N_NODES * HD];
__device__ float g_deg[N_NODES];
__device__ float g_P[(size_t)N_NODES * HD];
__device__ float g_Q[(size_t)N_NODES * HD];
__device__ float g_R[(size_t)E_EDGES * HD];
__device__ float g_H[(size_t)N_NODES * HD];
__device__ float g_W2p[HD * HD];
__device__ float g_d2[HD];

// Pre-split weight planes (hi/lo TF32). Flat layout (offsets = boundaries):
//   w1  @ 0       (320*128 = 40960)
//   uw1 @ 40960   (256*128 = 32768)   [uw1b rows at 57344]
//   uw2 @ 73728   (128*128 = 16384)
//   w2  @ 90112   (128*128 = 16384)
//   W2p @ 106496  (128*128 = 16384)
#define OFF_W1   0
#define OFF_UW1  40960
#define OFF_UW1B 57344
#define OFF_UW2  73728
#define OFF_W2   90112
#define OFF_W2P  106496
#define N_SPLIT_IN 106496
__device__ float g_Whi[122880];
__device__ float g_Wlo[122880];

// ---------------- helpers ----------------
__device__ __forceinline__ void red_add_v4(float* p, float a, float b, float c, float d) {
    asm volatile("red.global.add.v4.f32 [%0], {%1, %2, %3, %4};"
                 :: "l"(p), "f"(a), "f"(b), "f"(c), "f"(d) : "memory");
}
__device__ __forceinline__ void red_add_f32(float* p, float v) {
    asm volatile("red.global.add.f32 [%0], %1;" :: "l"(p), "f"(v) : "memory");
}
__device__ __forceinline__ float2 split_f(float x) {
    uint32_t hi;
    asm("cvt.rna.tf32.f32 %0, %1;" : "=r"(hi) : "f"(x));
    float h = __uint_as_float(hi);
    float r = x - h;
    uint32_t lo;
    asm("cvt.rna.tf32.f32 %0, %1;" : "=r"(lo) : "f"(r));
    return make_float2(h, __uint_as_float(lo));
}
__device__ __forceinline__ void mma_tf32(float d[4], const uint32_t a[4], const uint32_t b[2]) {
    asm("mma.sync.aligned.m16n8k8.row.col.f32.tf32.tf32.f32 "
        "{%0,%1,%2,%3}, {%4,%5,%6,%7}, {%8,%9}, {%0,%1,%2,%3};"
        : "+f"(d[0]), "+f"(d[1]), "+f"(d[2]), "+f"(d[3])
        : "r"(a[0]), "r"(a[1]), "r"(a[2]), "r"(a[3]), "r"(b[0]), "r"(b[1]));
}
__device__ __forceinline__ void cp_async16(void* smem, const void* gmem) {
    uint32_t s = (uint32_t)__cvta_generic_to_shared(smem);
    asm volatile("cp.async.cg.shared.global [%0], [%1], 16;" :: "r"(s), "l"(gmem));
}
#define CP_COMMIT() asm volatile("cp.async.commit_group;")
#define CP_WAIT1()  asm volatile("cp.async.wait_group 1;")

__global__ void zero_kernel() {
    float4* p = reinterpret_cast<float4*>(g_hagg);
    const int n4 = N_NODES * HD / 4;
    for (int i = blockIdx.x * blockDim.x + threadIdx.x; i < n4;
         i += gridDim.x * blockDim.x)
        p[i] = make_float4(0.f, 0.f, 0.f, 0.f);
    for (int i = blockIdx.x * blockDim.x + threadIdx.x; i < N_NODES;
         i += gridDim.x * blockDim.x)
        g_deg[i] = 0.f;
}

// Split all 4 input weight matrices in one launch. Flat index == plane offset.
__global__ void split_all_kernel(const float* __restrict__ w1,
                                 const float* __restrict__ uw1,
                                 const float* __restrict__ uw2,
                                 const float* __restrict__ w2)
{
    int i = blockIdx.x * blockDim.x + threadIdx.x;
    if (i >= N_SPLIT_IN) return;
    float v;
    if (i < OFF_UW1)       v = w1[i];
    else if (i < OFF_UW2)  v = uw1[i - OFF_UW1];
    else if (i < OFF_W2)   v = uw2[i - OFF_UW2];
    else                   v = w2[i - OFF_W2];
    float2 s = split_f(v);
    g_Whi[i] = s.x;
    g_Wlo[i] = s.y;
}

__global__ void split_kernel(const float* __restrict__ src, int n, int off) {
    int i = blockIdx.x * blockDim.x + threadIdx.x;
    if (i < n) {
        float2 s = split_f(src[i]);
        g_Whi[off + i] = s.x;
        g_Wlo[off + i] = s.y;
    }
}

__global__ void d2_kernel(const float* __restrict__ uw1, const float* __restrict__ b2) {
    int j = threadIdx.x;
    float s = 0.f;
    for (int k = 0; k < HD; k++)
        s = fmaf(b2[k], uw1[(ND + k) * HD + j], s);
    g_d2[j] = s;
}

// ---------------------------------------------------------------------------
// gemm_tc: C[M][128] = A[M][K] @ W[K][128] (+bias)(+resid).  (unchanged R8)
// ---------------------------------------------------------------------------
__global__ __launch_bounds__(256, 2) void gemm_tc(
    const float* __restrict__ A, int M, int K,
    int wOff, const float* __restrict__ bias,
    const float* __restrict__ resid, float* __restrict__ C)
{
    __shared__ float As[2][64][20];
    __shared__ float Whs[2][16][136];
    __shared__ float Wls[2][16][136];

    const float* Whi = g_Whi + wOff;
    const float* Wlo = g_Wlo + wOff;

    const int tid = threadIdx.x;
    const int lane = tid & 31, warp = tid >> 5;
    const int wm = warp >> 2, wn = warp & 3;
    const int g = lane >> 2, tig = lane & 3;
    const long rBase = (long)blockIdx.x * 64;

    const int arow = tid >> 2, akq = tid & 3;
    long gArow = rBase + arow; if (gArow >= M) gArow = M - 1;
    const int wkr = tid >> 5, wcc = tid & 31;

    const int nChunks = K >> 4;

    float d[2][4][4];
    #pragma unroll
    for (int mf = 0; mf < 2; mf++)
        #pragma unroll
        for (int nf = 0; nf < 4; nf++)
            #pragma unroll
            for (int q = 0; q < 4; q++) d[mf][nf][q] = 0.f;

    cp_async16(&As[0][arow][akq * 4], A + gArow * K + akq * 4);
    cp_async16(&Whs[0][wkr][wcc * 4],     Whi + (long)wkr * 128 + wcc * 4);
    cp_async16(&Whs[0][wkr + 8][wcc * 4], Whi + (long)(wkr + 8) * 128 + wcc * 4);
    cp_async16(&Wls[0][wkr][wcc * 4],     Wlo + (long)wkr * 128 + wcc * 4);
    cp_async16(&Wls[0][wkr + 8][wcc * 4], Wlo + (long)(wkr + 8) * 128 + wcc * 4);
    CP_COMMIT();

    for (int c = 0; c < nChunks; c++) {
        if (c + 1 < nChunks) {
            int kc = (c + 1) * 16, buf = (c + 1) & 1;
            cp_async16(&As[buf][arow][akq * 4], A + gArow * K + kc + akq * 4);
            cp_async16(&Whs[buf][wkr][wcc * 4],     Whi + (long)(kc + wkr) * 128 + wcc * 4);
            cp_async16(&Whs[buf][wkr + 8][wcc * 4], Whi + (long)(kc + 8 + wkr) * 128 + wcc * 4);
            cp_async16(&Wls[buf][wkr][wcc * 4],     Wlo + (long)(kc + wkr) * 128 + wcc * 4);
            cp_async16(&Wls[buf][wkr + 8][wcc * 4], Wlo + (long)(kc + 8 + wkr) * 128 + wcc * 4);
        }
        CP_COMMIT();
        CP_WAIT1();
        __syncthreads();
        const int buf = c & 1;
        #pragma unroll
        for (int k8 = 0; k8 < 16; k8 += 8) {
            uint32_t ahi[2][4], alo[2][4], bhi[4][2], blo[4][2];
            #pragma unroll
            for (int mf = 0; mf < 2; mf++) {
                int mb = wm * 32 + mf * 16;
                float2 s0 = split_f(As[buf][mb + g][k8 + tig]);
                float2 s1 = split_f(As[buf][mb + 8 + g][k8 + tig]);
                float2 s2 = split_f(As[buf][mb + g][k8 + tig + 4]);
                float2 s3 = split_f(As[buf][mb + 8 + g][k8 + tig + 4]);
                ahi[mf][0] = __float_as_uint(s0.x); alo[mf][0] = __float_as_uint(s0.y);
                ahi[mf][1] = __float_as_uint(s1.x); alo[mf][1] = __float_as_uint(s1.y);
                ahi[mf][2] = __float_as_uint(s2.x); alo[mf][2] = __float_as_uint(s2.y);
                ahi[mf][3] = __float_as_uint(s3.x); alo[mf][3] = __float_as_uint(s3.y);
            }
            #pragma unroll
            for (int nf = 0; nf < 4; nf++) {
                int nb = wn * 32 + nf * 8;
                bhi[nf][0] = __float_as_uint(Whs[buf][k8 + tig][nb + g]);
                bhi[nf][1] = __float_as_uint(Whs[buf][k8 + tig + 4][nb + g]);
                blo[nf][0] = __float_as_uint(Wls[buf][k8 + tig][nb + g]);
                blo[nf][1] = __float_as_uint(Wls[buf][k8 + tig + 4][nb + g]);
            }
            #pragma unroll
            for (int mf = 0; mf < 2; mf++)
                #pragma unroll
                for (int nf = 0; nf < 4; nf++) {
                    mma_tf32(d[mf][nf], ahi[mf], bhi[nf]);
                    mma_tf32(d[mf][nf], alo[mf], bhi[nf]);
                    mma_tf32(d[mf][nf], ahi[mf], blo[nf]);
                }
        }
        __syncthreads();
    }

    #pragma unroll
    for (int mf = 0; mf < 2; mf++) {
        #pragma unroll
        for (int r2 = 0; r2 < 2; r2++) {
            long m = rBase + wm * 32 + mf * 16 + g + r2 * 8;
            if (m < M) {
                #pragma unroll
                for (int nf = 0; nf < 4; nf++) {
                    int n = wn * 32 + nf * 8 + 2 * tig;
                    float v0 = d[mf][nf][r2 * 2];
                    float v1 = d[mf][nf][r2 * 2 + 1];
                    if (bias)  { v0 += bias[n];  v1 += bias[n + 1]; }
                    if (resid) { float2 rr = *(const float2*)(resid + m * 128 + n);
                                 v0 += rr.x; v1 += rr.y; }
                    *(float2*)(C + m * 128 + n) = make_float2(v0, v1);
                }
            }
        }
    }
}

// ---------------------------------------------------------------------------
// upd_fused: g_H = relu(LN(nf@uw1a + hagg@W2p + ub1 + deg*d2) * g2 + be2)
// 16 K-chunks: chunks 0-7 A=nf/W=uw1a; chunks 8-15 A=hagg/W=W2p.
// Epilogue stages the 64x128 tile in SMEM (aliased), warp-per-row LN.
// ---------------------------------------------------------------------------
__global__ __launch_bounds__(256, 2) void upd_fused(
    const float* __restrict__ nf, const float* __restrict__ ub1,
    const float* __restrict__ g2, const float* __restrict__ be2)
{
    __shared__ float pool[11264];   // As(2560) | Whs(4352) | Wls(4352); Cs aliases
    #define ASP(b, r, c)  pool[(b) * 1280 + (r) * 20 + (c)]
    #define WHSP(b, r, c) pool[2560 + (b) * 2176 + (r) * 136 + (c)]
    #define WLSP(b, r, c) pool[6912 + (b) * 2176 + (r) * 136 + (c)]
    #define CSP(r, c)     pool[(r) * 132 + (c)]

    const float* haggp = g_hagg;
    const int tid = threadIdx.x;
    const int lane = tid & 31, warp = tid >> 5;
    const int wm = warp >> 2, wn = warp & 3;
    const int g = lane >> 2, tig = lane & 3;
    const long rBase = (long)blockIdx.x * 64;

    const int arow = tid >> 2, akq = tid & 3;
    long gArow = rBase + arow; if (gArow >= N_NODES) gArow = N_NODES - 1;
    const int wkr = tid >> 5, wcc = tid & 31;

    float d[2][4][4];
    #pragma unroll
    for (int mf = 0; mf < 2; mf++)
        #pragma unroll
        for (int nf = 0; nf < 4; nf++)
            #pragma unroll
            for (int q = 0; q < 4; q++) d[mf][nf][q] = 0.f;

    // chunk c in [0,16): A/W switch at c==8
    {
        const float* A0 = nf;
        const float* Wh0 = g_Whi + OFF_UW1;
        const float* Wl0 = g_Wlo + OFF_UW1;
        cp_async16(&ASP(0, arow, akq * 4), A0 + gArow * HD + akq * 4);
        cp_async16(&WHSP(0, wkr, wcc * 4),     Wh0 + (long)wkr * 128 + wcc * 4);
        cp_async16(&WHSP(0, wkr + 8, wcc * 4), Wh0 + (long)(wkr + 8) * 128 + wcc * 4);
        cp_async16(&WLSP(0, wkr, wcc * 4),     Wl0 + (long)wkr * 128 + wcc * 4);
        cp_async16(&WLSP(0, wkr + 8, wcc * 4), Wl0 + (long)(wkr + 8) * 128 + wcc * 4);
        CP_COMMIT();
    }

    for (int c = 0; c < 16; c++) {
        if (c + 1 < 16) {
            int cn = c + 1, buf = cn & 1;
            int kc = (cn & 7) * 16;
            const float* An  = (cn < 8) ? nf : haggp;
            const float* Whn = g_Whi + ((cn < 8) ? OFF_UW1 : OFF_W2P);
            const float* Wln = g_Wlo + ((cn < 8) ? OFF_UW1 : OFF_W2P);
            cp_async16(&ASP(buf, arow, akq * 4), An + gArow * HD + kc + akq * 4);
            cp_async16(&WHSP(buf, wkr, wcc * 4),     Whn + (long)(kc + wkr) * 128 + wcc * 4);
            cp_async16(&WHSP(buf, wkr + 8, wcc * 4), Whn + (long)(kc + 8 + wkr) * 128 + wcc * 4);
            cp_async16(&WLSP(buf, wkr, wcc * 4),     Wln + (long)(kc + wkr) * 128 + wcc * 4);
            cp_async16(&WLSP(buf, wkr + 8, wcc * 4), Wln + (long)(kc + 8 + wkr) * 128 + wcc * 4);
        }
        CP_COMMIT();
        CP_WAIT1();
        __syncthreads();
        const int buf = c & 1;
        #pragma unroll
        for (int k8 = 0; k8 < 16; k8 += 8) {
            uint32_t ahi[2][4], alo[2][4], bhi[4][2], blo[4][2];
            #pragma unroll
            for (int mf = 0; mf < 2; mf++) {
                int mb = wm * 32 + mf * 16;
                float2 s0 = split_f(ASP(buf, mb + g, k8 + tig));
                float2 s1 = split_f(ASP(buf, mb + 8 + g, k8 + tig));
                float2 s2 = split_f(ASP(buf, mb + g, k8 + tig + 4));
                float2 s3 = split_f(ASP(buf, mb + 8 + g, k8 + tig + 4));
                ahi[mf][0] = __float_as_uint(s0.x); alo[mf][0] = __float_as_uint(s0.y);
                ahi[mf][1] = __float_as_uint(s1.x); alo[mf][1] = __float_as_uint(s1.y);
                ahi[mf][2] = __float_as_uint(s2.x); alo[mf][2] = __float_as_uint(s2.y);
                ahi[mf][3] = __float_as_uint(s3.x); alo[mf][3] = __float_as_uint(s3.y);
            }
            #pragma unroll
            for (int nf = 0; nf < 4; nf++) {
                int nb = wn * 32 + nf * 8;
                bhi[nf][0] = __float_as_uint(WHSP(buf, k8 + tig, nb + g));
                bhi[nf][1] = __float_as_uint(WHSP(buf, k8 + tig + 4, nb + g));
                blo[nf][0] = __float_as_uint(WLSP(buf, k8 + tig, nb + g));
                blo[nf][1] = __float_as_uint(WLSP(buf, k8 + tig + 4, nb + g));
            }
            #pragma unroll
            for (int mf = 0; mf < 2; mf++)
                #pragma unroll
                for (int nf = 0; nf < 4; nf++) {
                    mma_tf32(d[mf][nf], ahi[mf], bhi[nf]);
                    mma_tf32(d[mf][nf], alo[mf], bhi[nf]);
                    mma_tf32(d[mf][nf], ahi[mf], blo[nf]);
                }
        }
        __syncthreads();
    }

    // stage tile into SMEM (aliases compute buffers — loop is done)
    #pragma unroll
    for (int mf = 0; mf < 2; mf++)
        #pragma unroll
        for (int r2 = 0; r2 < 2; r2++) {
            int lr = wm * 32 + mf * 16 + g + r2 * 8;
            #pragma unroll
            for (int nf = 0; nf < 4; nf++) {
                int n = wn * 32 + nf * 8 + 2 * tig;
                CSP(lr, n)     = d[mf][nf][r2 * 2];
                CSP(lr, n + 1) = d[mf][nf][r2 * 2 + 1];
            }
        }
    __syncthreads();

    // warp-per-row LN over the staged tile
    #pragma unroll
    for (int r8 = 0; r8 < 8; r8++) {
        int lr = warp * 8 + r8;
        long row = rBase + lr;
        long rowc = row < N_NODES ? row : N_NODES - 1;
        float dg = g_deg[rowc];
        int cc = lane * 4;
        float4 v = *(float4*)&CSP(lr, cc);
        float4 ub = *(const float4*)&ub1[cc];
        float4 dd = *(const float4*)&g_d2[cc];
        v.x += ub.x + dg * dd.x; v.y += ub.y + dg * dd.y;
        v.z += ub.z + dg * dd.z; v.w += ub.w + dg * dd.w;
        float s1 = v.x + v.y + v.z + v.w;
        float ss = v.x * v.x + v.y * v.y + v.z * v.z + v.w * v.w;
        #pragma unroll
        for (int o = 16; o >= 1; o >>= 1) {
            s1 += __shfl_xor_sync(0xffffffffu, s1, o);
            ss += __shfl_xor_sync(0xffffffffu, ss, o);
        }
        float mean = s1 * (1.0f / HD);
        float var  = ss * (1.0f / HD) - mean * mean;
        float rstd = rsqrtf(var + LN_EPS);
        if (row < N_NODES) {
            float4 gg = *(const float4*)&g2[cc];
            float4 bb = *(const float4*)&be2[cc];
            float4 h;
            h.x = fmaxf((v.x - mean) * rstd * gg.x + bb.x, 0.f);
            h.y = fmaxf((v.y - mean) * rstd * gg.y + bb.y, 0.f);
            h.z = fmaxf((v.z - mean) * rstd * gg.z + bb.z, 0.f);
            h.w = fmaxf((v.w - mean) * rstd * gg.w + bb.w, 0.f);
            *(float4*)(g_H + row * HD + cc) = h;
        }
    }
}

// ---------------------------------------------------------------------------
// Edge kernel: one warp per UNDIRECTED edge; both directions.
// ---------------------------------------------------------------------------
__global__ __launch_bounds__(256) void edge_kernel(
    const int* __restrict__ eidx,
    const float* __restrict__ g1, const float* __restrict__ be1)
{
    const int wid = threadIdx.x >> 5, lane = threadIdx.x & 31;
    const long e = (long)blockIdx.x * 8 + wid;
    const int s = eidx[e], t = eidx[E_EDGES + e];

    float4 ps = *(const float4*)(g_P + (long)s * HD + lane * 4);
    float4 pt = *(const float4*)(g_P + (long)t * HD + lane * 4);
    float4 qs = *(const float4*)(g_Q + (long)s * HD + lane * 4);
    float4 qt = *(const float4*)(g_Q + (long)t * HD + lane * 4);
    float4 r  = *(const float4*)(g_R + e * HD + lane * 4);
    float4 gg = *(const float4*)&g1[lane * 4];
    float4 bb = *(const float4*)&be1[lane * 4];

    float4 vf = make_float4(ps.x + qt.x + r.x, ps.y + qt.y + r.y,
                            ps.z + qt.z + r.z, ps.w + qt.w + r.w);
    float4 vb = make_float4(pt.x + qs.x + r.x, pt.y + qs.y + r.y,
                            pt.z + qs.z + r.z, pt.w + qs.w + r.w);

    float s1f = vf.x + vf.y + vf.z + vf.w;
    float ssf = vf.x * vf.x + vf.y * vf.y + vf.z * vf.z + vf.w * vf.w;
    float s1b = vb.x + vb.y + vb.z + vb.w;
    float ssb = vb.x * vb.x + vb.y * vb.y + vb.z * vb.z + vb.w * vb.w;
    #pragma unroll
    for (int o = 16; o >= 1; o >>= 1) {
        s1f += __shfl_xor_sync(0xffffffffu, s1f, o);
        ssf += __shfl_xor_sync(0xffffffffu, ssf, o);
        s1b += __shfl_xor_sync(0xffffffffu, s1b, o);
        ssb += __shfl_xor_sync(0xffffffffu, ssb, o);
    }
    {
        float mean = s1f * (1.0f / HD);
        float var  = ssf * (1.0f / HD) - mean * mean;
        float rstd = rsqrtf(var + LN_EPS);
        float h0 = fmaxf((vf.x - mean) * rstd * gg.x + bb.x, 0.f);
        float h1 = fmaxf((vf.y - mean) * rstd * gg.y + bb.y, 0.f);
        float h2 = fmaxf((vf.z - mean) * rstd * gg.z + bb.z, 0.f);
        float h3 = fmaxf((vf.w - mean) * rstd * gg.w + bb.w, 0.f);
        red_add_v4(g_hagg + (long)t * HD + lane * 4, h0, h1, h2, h3);
    }
    {
        float mean = s1b * (1.0f / HD);
        float var  = ssb * (1.0f / HD) - mean * mean;
        float rstd = rsqrtf(var + LN_EPS);
        float h0 = fmaxf((vb.x - mean) * rstd * gg.x + bb.x, 0.f);
        float h1 = fmaxf((vb.y - mean) * rstd * gg.y + bb.y, 0.f);
        float h2 = fmaxf((vb.z - mean) * rstd * gg.z + bb.z, 0.f);
        float h3 = fmaxf((vb.w - mean) * rstd * gg.w + bb.w, 0.f);
        red_add_v4(g_hagg + (long)s * HD + lane * 4, h0, h1, h2, h3);
    }
    if (lane == 0) { red_add_f32(g_deg + t, 1.0f); red_add_f32(g_deg + s, 1.0f); }
}

extern "C" void kernel_launch(void* const* d_in, const int* in_sizes, int n_in,
                              void* d_out, int out_size)
{
    const float* nf   = (const float*)d_in[0];
    const float* ef   = (const float*)d_in[1];
    const int*   eidx = (const int*)  d_in[2];
    const float* w1   = (const float*)d_in[3];
    const float* b1   = (const float*)d_in[4];
    const float* g1   = (const float*)d_in[5];
    const float* be1  = (const float*)d_in[6];
    const float* w2   = (const float*)d_in[7];
    const float* b2   = (const float*)d_in[8];
    const float* uw1  = (const float*)d_in[9];
    const float* ub1  = (const float*)d_in[10];
    const float* g2   = (const float*)d_in[11];
    const float* be2  = (const float*)d_in[12];
    const float* uw2  = (const float*)d_in[13];
    const float* ub2  = (const float*)d_in[14];
    float* out = (float*)d_out;

    float *dP, *dQ, *dR, *dH, *dW2p;
    cudaGetSymbolAddress((void**)&dP,    g_P);
    cudaGetSymbolAddress((void**)&dQ,    g_Q);
    cudaGetSymbolAddress((void**)&dR,    g_R);
    cudaGetSymbolAddress((void**)&dH,    g_H);
    cudaGetSymbolAddress((void**)&dW2p,  g_W2p);

    const int gN = (N_NODES + 63) / 64;   // 1563
    const int gE = (E_EDGES + 63) / 64;   // 6250

    zero_kernel<<<592, 256>>>();
    d2_kernel<<<1, 128>>>(uw1, b2);
    split_all_kernel<<<(N_SPLIT_IN + 255) / 256, 256>>>(w1, uw1, uw2, w2);
    // W2p = W2 @ uw1b, then split it
    gemm_tc<<<2, 256>>>(w2, 128, HD, OFF_UW1B, nullptr, nullptr, dW2p);
    split_kernel<<<(128 * 128 + 255) / 256, 256>>>(dW2p, 128 * 128, OFF_W2P);
    // P = nf@W1a, Q = nf@W1b, R = ef@W1c + b1
    gemm_tc<<<gN, 256>>>(nf, N_NODES, ND, OFF_W1, nullptr, nullptr, dP);
    gemm_tc<<<gN, 256>>>(nf, N_NODES, ND, OFF_W1 + ND * HD, nullptr, nullptr, dQ);
    gemm_tc<<<gE, 256>>>(ef, E_EDGES, ED, OFF_W1 + 2 * ND * HD, b1, nullptr, dR);
    // edges: gather + LN + scatter
    edge_kernel<<<E_EDGES / 8, 256>>>(eidx, g1, be1);
    // fused update MLP layer-1 + LN
    upd_fused<<<gN, 256>>>(nf, ub1, g2, be2);
    // out = H@uw2 + ub2 + nf
    gemm_tc<<<gN, 256>>>(dH, N_NODES, HD, OFF_UW2, ub2, nf, out);
}

// round 10
// speedup vs baseline: 1.3929x; 1.0774x over previous
#include <cuda_runtime.h>
#include <cuda_fp16.h>
#include <math.h>
#include <stdint.h>

#define N_NODES 100000
#define E_EDGES 400000
#define ND 128
#define ED 64
#define HD 128
#define LN_EPS 1e-5f

// Scratch (__device__ globals: allocation-free rule)
__device__ float  g_hagg[(size_t)N_NODES * HD];
__device__ float  g_deg[N_NODES];
__device__ __half g_PQh[(size_t)N_NODES * 256];   // [node][0:128]=P, [128:256]=Q
__device__ __half g_Rh[(size_t)E_EDGES * HD];     // ef @ W1c + b1
__device__ float  g_H[(size_t)N_NODES * HD];
__device__ float  g_d2[HD];

// Pre-split weight planes (hi/lo TF32). Flat layout:
//   w1  @ 0       (320*128 = 40960)
//   uw1 @ 40960   (256*128 = 32768)
//   uw2 @ 73728   (128*128 = 16384)
//   W2p @ 90112   (128*128 = 16384)
#define OFF_W1   0
#define OFF_UW1  40960
#define OFF_UW2  73728
#define OFF_W2P  90112
#define N_SPLIT_IN 90112
__device__ float g_Whi[106496];
__device__ float g_Wlo[106496];

// ---------------- helpers ----------------
__device__ __forceinline__ void red_add_v4(float* p, float a, float b, float c, float d) {
    asm volatile("red.global.add.v4.f32 [%0], {%1, %2, %3, %4};"
                 :: "l"(p), "f"(a), "f"(b), "f"(c), "f"(d) : "memory");
}
__device__ __forceinline__ void red_add_f32(float* p, float v) {
    asm volatile("red.global.add.f32 [%0], %1;" :: "l"(p), "f"(v) : "memory");
}
__device__ __forceinline__ float2 split_f(float x) {
    uint32_t hi;
    asm("cvt.rna.tf32.f32 %0, %1;" : "=r"(hi) : "f"(x));
    float h = __uint_as_float(hi);
    float r = x - h;
    uint32_t lo;
    asm("cvt.rna.tf32.f32 %0, %1;" : "=r"(lo) : "f"(r));
    return make_float2(h, __uint_as_float(lo));
}
__device__ __forceinline__ void mma_tf32(float d[4], const uint32_t a[4], const uint32_t b[2]) {
    asm("mma.sync.aligned.m16n8k8.row.col.f32.tf32.tf32.f32 "
        "{%0,%1,%2,%3}, {%4,%5,%6,%7}, {%8,%9}, {%0,%1,%2,%3};"
        : "+f"(d[0]), "+f"(d[1]), "+f"(d[2]), "+f"(d[3])
        : "r"(a[0]), "r"(a[1]), "r"(a[2]), "r"(a[3]), "r"(b[0]), "r"(b[1]));
}
__device__ __forceinline__ void cp_async16(void* smem, const void* gmem) {
    uint32_t s = (uint32_t)__cvta_generic_to_shared(smem);
    asm volatile("cp.async.cg.shared.global [%0], [%1], 16;" :: "r"(s), "l"(gmem));
}
#define CP_COMMIT() asm volatile("cp.async.commit_group;")
#define CP_WAIT1()  asm volatile("cp.async.wait_group 1;")

__device__ __forceinline__ float4 ld_half4(const __half* p) {
    uint2 u = *(const uint2*)p;
    __half2 a = *reinterpret_cast<__half2*>(&u.x);
    __half2 b = *reinterpret_cast<__half2*>(&u.y);
    float2 fa = __half22float2(a), fb = __half22float2(b);
    return make_float4(fa.x, fa.y, fb.x, fb.y);
}

__global__ void zero_kernel() {
    float4* p = reinterpret_cast<float4*>(g_hagg);
    const int n4 = N_NODES * HD / 4;
    for (int i = blockIdx.x * blockDim.x + threadIdx.x; i < n4;
         i += gridDim.x * blockDim.x)
        p[i] = make_float4(0.f, 0.f, 0.f, 0.f);
    for (int i = blockIdx.x * blockDim.x + threadIdx.x; i < N_NODES;
         i += gridDim.x * blockDim.x)
        g_deg[i] = 0.f;
}

// Split w1, uw1, uw2 into hi/lo planes in one launch.
__global__ void split_all_kernel(const float* __restrict__ w1,
                                 const float* __restrict__ uw1,
                                 const float* __restrict__ uw2)
{
    int i = blockIdx.x * blockDim.x + threadIdx.x;
    if (i >= N_SPLIT_IN) return;
    float v;
    if (i < OFF_UW1)       v = w1[i];
    else if (i < OFF_UW2)  v = uw1[i - OFF_UW1];
    else                   v = uw2[i - OFF_UW2];
    float2 s = split_f(v);
    g_Whi[i] = s.x;
    g_Wlo[i] = s.y;
}

__global__ void d2_kernel(const float* __restrict__ uw1, const float* __restrict__ b2) {
    int j = threadIdx.x;
    float s = 0.f;
    for (int k = 0; k < HD; k++)
        s = fmaf(b2[k], uw1[(ND + k) * HD + j], s);
    g_d2[j] = s;
}

// W2p = W2 @ uw1b computed + split in one kernel. grid=128, block=128.
__global__ void w2p_kernel(const float* __restrict__ w2, const float* __restrict__ uw1) {
    int k = blockIdx.x, n = threadIdx.x;
    float s = 0.f;
    for (int m = 0; m < HD; m++)
        s = fmaf(w2[k * HD + m], uw1[(ND + m) * HD + n], s);
    float2 sp = split_f(s);
    g_Whi[OFF_W2P + k * HD + n] = sp.x;
    g_Wlo[OFF_W2P + k * HD + n] = sp.y;
}

// ---------------------------------------------------------------------------
// gemm_tc: D = A[M][K] @ W[K][128] (+bias).  Output either:
//   Ch != nullptr: half, row stride ldc, column offset colOff
//   else: float C[M][128] (+resid)
// 3xTF32 mma.sync; A split at fragment load; W pre-split planes; cp.async x2.
// ---------------------------------------------------------------------------
__global__ __launch_bounds__(256, 2) void gemm_tc(
    const float* __restrict__ A, int M, int K,
    int wOff, const float* __restrict__ bias,
    const float* __restrict__ resid, float* __restrict__ C,
    __half* __restrict__ Ch, int ldc, int colOff)
{
    __shared__ float As[2][64][20];
    __shared__ float Whs[2][16][136];
    __shared__ float Wls[2][16][136];

    const float* Whi = g_Whi + wOff;
    const float* Wlo = g_Wlo + wOff;

    const int tid = threadIdx.x;
    const int lane = tid & 31, warp = tid >> 5;
    const int wm = warp >> 2, wn = warp & 3;
    const int g = lane >> 2, tig = lane & 3;
    const long rBase = (long)blockIdx.x * 64;

    const int arow = tid >> 2, akq = tid & 3;
    long gArow = rBase + arow; if (gArow >= M) gArow = M - 1;
    const int wkr = tid >> 5, wcc = tid & 31;

    const int nChunks = K >> 4;

    float d[2][4][4];
    #pragma unroll
    for (int mf = 0; mf < 2; mf++)
        #pragma unroll
        for (int nf = 0; nf < 4; nf++)
            #pragma unroll
            for (int q = 0; q < 4; q++) d[mf][nf][q] = 0.f;

    cp_async16(&As[0][arow][akq * 4], A + gArow * K + akq * 4);
    cp_async16(&Whs[0][wkr][wcc * 4],     Whi + (long)wkr * 128 + wcc * 4);
    cp_async16(&Whs[0][wkr + 8][wcc * 4], Whi + (long)(wkr + 8) * 128 + wcc * 4);
    cp_async16(&Wls[0][wkr][wcc * 4],     Wlo + (long)wkr * 128 + wcc * 4);
    cp_async16(&Wls[0][wkr + 8][wcc * 4], Wlo + (long)(wkr + 8) * 128 + wcc * 4);
    CP_COMMIT();

    for (int c = 0; c < nChunks; c++) {
        if (c + 1 < nChunks) {
            int kc = (c + 1) * 16, buf = (c + 1) & 1;
            cp_async16(&As[buf][arow][akq * 4], A + gArow * K + kc + akq * 4);
            cp_async16(&Whs[buf][wkr][wcc * 4],     Whi + (long)(kc + wkr) * 128 + wcc * 4);
            cp_async16(&Whs[buf][wkr + 8][wcc * 4], Whi + (long)(kc + 8 + wkr) * 128 + wcc * 4);
            cp_async16(&Wls[buf][wkr][wcc * 4],     Wlo + (long)(kc + wkr) * 128 + wcc * 4);
            cp_async16(&Wls[buf][wkr + 8][wcc * 4], Wlo + (long)(kc + 8 + wkr) * 128 + wcc * 4);
        }
        CP_COMMIT();
        CP_WAIT1();
        __syncthreads();
        const int buf = c & 1;
        #pragma unroll
        for (int k8 = 0; k8 < 16; k8 += 8) {
            uint32_t ahi[2][4], alo[2][4], bhi[4][2], blo[4][2];
            #pragma unroll
            for (int mf = 0; mf < 2; mf++) {
                int mb = wm * 32 + mf * 16;
                float2 s0 = split_f(As[buf][mb + g][k8 + tig]);
                float2 s1 = split_f(As[buf][mb + 8 + g][k8 + tig]);
                float2 s2 = split_f(As[buf][mb + g][k8 + tig + 4]);
                float2 s3 = split_f(As[buf][mb + 8 + g][k8 + tig + 4]);
                ahi[mf][0] = __float_as_uint(s0.x); alo[mf][0] = __float_as_uint(s0.y);
                ahi[mf][1] = __float_as_uint(s1.x); alo[mf][1] = __float_as_uint(s1.y);
                ahi[mf][2] = __float_as_uint(s2.x); alo[mf][2] = __float_as_uint(s2.y);
                ahi[mf][3] = __float_as_uint(s3.x); alo[mf][3] = __float_as_uint(s3.y);
            }
            #pragma unroll
            for (int nf = 0; nf < 4; nf++) {
                int nb = wn * 32 + nf * 8;
                bhi[nf][0] = __float_as_uint(Whs[buf][k8 + tig][nb + g]);
                bhi[nf][1] = __float_as_uint(Whs[buf][k8 + tig + 4][nb + g]);
                blo[nf][0] = __float_as_uint(Wls[buf][k8 + tig][nb + g]);
                blo[nf][1] = __float_as_uint(Wls[buf][k8 + tig + 4][nb + g]);
            }
            #pragma unroll
            for (int mf = 0; mf < 2; mf++)
                #pragma unroll
                for (int nf = 0; nf < 4; nf++) {
                    mma_tf32(d[mf][nf], ahi[mf], bhi[nf]);
                    mma_tf32(d[mf][nf], alo[mf], bhi[nf]);
                    mma_tf32(d[mf][nf], ahi[mf], blo[nf]);
                }
        }
        __syncthreads();
    }

    #pragma unroll
    for (int mf = 0; mf < 2; mf++) {
        #pragma unroll
        for (int r2 = 0; r2 < 2; r2++) {
            long m = rBase + wm * 32 + mf * 16 + g + r2 * 8;
            if (m < M) {
                #pragma unroll
                for (int nf = 0; nf < 4; nf++) {
                    int n = wn * 32 + nf * 8 + 2 * tig;
                    float v0 = d[mf][nf][r2 * 2];
                    float v1 = d[mf][nf][r2 * 2 + 1];
                    if (bias) { v0 += bias[n]; v1 += bias[n + 1]; }
                    if (Ch) {
                        *(__half2*)(Ch + m * ldc + colOff + n) = __floats2half2_rn(v0, v1);
                    } else {
                        if (resid) { float2 rr = *(const float2*)(resid + m * 128 + n);
                                     v0 += rr.x; v1 += rr.y; }
                        *(float2*)(C + m * 128 + n) = make_float2(v0, v1);
                    }
                }
            }
        }
    }
}

// ---------------------------------------------------------------------------
// upd_fused: g_H = relu(LN(nf@uw1a + hagg@W2p + ub1 + deg*d2) * g2 + be2)
// 16 K-chunks: 0-7 A=nf/W=uw1a; 8-15 A=hagg/W=W2p. SMEM-staged LN epilogue.
// ---------------------------------------------------------------------------
__global__ __launch_bounds__(256, 2) void upd_fused(
    const float* __restrict__ nf, const float* __restrict__ ub1,
    const float* __restrict__ g2, const float* __restrict__ be2)
{
    __shared__ float pool[11264];
    #define ASP(b, r, c)  pool[(b) * 1280 + (r) * 20 + (c)]
    #define WHSP(b, r, c) pool[2560 + (b) * 2176 + (r) * 136 + (c)]
    #define WLSP(b, r, c) pool[6912 + (b) * 2176 + (r) * 136 + (c)]
    #define CSP(r, c)     pool[(r) * 132 + (c)]

    const float* haggp = g_hagg;
    const int tid = threadIdx.x;
    const int lane = tid & 31, warp = tid >> 5;
    const int wm = warp >> 2, wn = warp & 3;
    const int g = lane >> 2, tig = lane & 3;
    const long rBase = (long)blockIdx.x * 64;

    const int arow = tid >> 2, akq = tid & 3;
    long gArow = rBase + arow; if (gArow >= N_NODES) gArow = N_NODES - 1;
    const int wkr = tid >> 5, wcc = tid & 31;

    float d[2][4][4];
    #pragma unroll
    for (int mf = 0; mf < 2; mf++)
        #pragma unroll
        for (int nf = 0; nf < 4; nf++)
            #pragma unroll
            for (int q = 0; q < 4; q++) d[mf][nf][q] = 0.f;

    {
        const float* Wh0 = g_Whi + OFF_UW1;
        const float* Wl0 = g_Wlo + OFF_UW1;
        cp_async16(&ASP(0, arow, akq * 4), nf + gArow * HD + akq * 4);
        cp_async16(&WHSP(0, wkr, wcc * 4),     Wh0 + (long)wkr * 128 + wcc * 4);
        cp_async16(&WHSP(0, wkr + 8, wcc * 4), Wh0 + (long)(wkr + 8) * 128 + wcc * 4);
        cp_async16(&WLSP(0, wkr, wcc * 4),     Wl0 + (long)wkr * 128 + wcc * 4);
        cp_async16(&WLSP(0, wkr + 8, wcc * 4), Wl0 + (long)(wkr + 8) * 128 + wcc * 4);
        CP_COMMIT();
    }

    for (int c = 0; c < 16; c++) {
        if (c + 1 < 16) {
            int cn = c + 1, buf = cn & 1;
            int kc = (cn & 7) * 16;
            const float* An  = (cn < 8) ? nf : haggp;
            const float* Whn = g_Whi + ((cn < 8) ? OFF_UW1 : OFF_W2P);
            const float* Wln = g_Wlo + ((cn < 8) ? OFF_UW1 : OFF_W2P);
            cp_async16(&ASP(buf, arow, akq * 4), An + gArow * HD + kc + akq * 4);
            cp_async16(&WHSP(buf, wkr, wcc * 4),     Whn + (long)(kc + wkr) * 128 + wcc * 4);
            cp_async16(&WHSP(buf, wkr + 8, wcc * 4), Whn + (long)(kc + 8 + wkr) * 128 + wcc * 4);
            cp_async16(&WLSP(buf, wkr, wcc * 4),     Wln + (long)(kc + wkr) * 128 + wcc * 4);
            cp_async16(&WLSP(buf, wkr + 8, wcc * 4), Wln + (long)(kc + 8 + wkr) * 128 + wcc * 4);
        }
        CP_COMMIT();
        CP_WAIT1();
        __syncthreads();
        const int buf = c & 1;
        #pragma unroll
        for (int k8 = 0; k8 < 16; k8 += 8) {
            uint32_t ahi[2][4], alo[2][4], bhi[4][2], blo[4][2];
            #pragma unroll
            for (int mf = 0; mf < 2; mf++) {
                int mb = wm * 32 + mf * 16;
                float2 s0 = split_f(ASP(buf, mb + g, k8 + tig));
                float2 s1 = split_f(ASP(buf, mb + 8 + g, k8 + tig));
                float2 s2 = split_f(ASP(buf, mb + g, k8 + tig + 4));
                float2 s3 = split_f(ASP(buf, mb + 8 + g, k8 + tig + 4));
                ahi[mf][0] = __float_as_uint(s0.x); alo[mf][0] = __float_as_uint(s0.y);
                ahi[mf][1] = __float_as_uint(s1.x); alo[mf][1] = __float_as_uint(s1.y);
                ahi[mf][2] = __float_as_uint(s2.x); alo[mf][2] = __float_as_uint(s2.y);
                ahi[mf][3] = __float_as_uint(s3.x); alo[mf][3] = __float_as_uint(s3.y);
            }
            #pragma unroll
            for (int nf2 = 0; nf2 < 4; nf2++) {
                int nb = wn * 32 + nf2 * 8;
                bhi[nf2][0] = __float_as_uint(WHSP(buf, k8 + tig, nb + g));
                bhi[nf2][1] = __float_as_uint(WHSP(buf, k8 + tig + 4, nb + g));
                blo[nf2][0] = __float_as_uint(WLSP(buf, k8 + tig, nb + g));
                blo[nf2][1] = __float_as_uint(WLSP(buf, k8 + tig + 4, nb + g));
            }
            #pragma unroll
            for (int mf = 0; mf < 2; mf++)
                #pragma unroll
                for (int nf2 = 0; nf2 < 4; nf2++) {
                    mma_tf32(d[mf][nf2], ahi[mf], bhi[nf2]);
                    mma_tf32(d[mf][nf2], alo[mf], bhi[nf2]);
                    mma_tf32(d[mf][nf2], ahi[mf], blo[nf2]);
                }
        }
        __syncthreads();
    }

    #pragma unroll
    for (int mf = 0; mf < 2; mf++)
        #pragma unroll
        for (int r2 = 0; r2 < 2; r2++) {
            int lr = wm * 32 + mf * 16 + g + r2 * 8;
            #pragma unroll
            for (int nf2 = 0; nf2 < 4; nf2++) {
                int n = wn * 32 + nf2 * 8 + 2 * tig;
                CSP(lr, n)     = d[mf][nf2][r2 * 2];
                CSP(lr, n + 1) = d[mf][nf2][r2 * 2 + 1];
            }
        }
    __syncthreads();

    #pragma unroll
    for (int r8 = 0; r8 < 8; r8++) {
        int lr = warp * 8 + r8;
        long row = rBase + lr;
        long rowc = row < N_NODES ? row : N_NODES - 1;
        float dg = g_deg[rowc];
        int cc = lane * 4;
        float4 v = *(float4*)&CSP(lr, cc);
        float4 ub = *(const float4*)&ub1[cc];
        float4 dd = *(const float4*)&g_d2[cc];
        v.x += ub.x + dg * dd.x; v.y += ub.y + dg * dd.y;
        v.z += ub.z + dg * dd.z; v.w += ub.w + dg * dd.w;
        float s1 = v.x + v.y + v.z + v.w;
        float ss = v.x * v.x + v.y * v.y + v.z * v.z + v.w * v.w;
        #pragma unroll
        for (int o = 16; o >= 1; o >>= 1) {
            s1 += __shfl_xor_sync(0xffffffffu, s1, o);
            ss += __shfl_xor_sync(0xffffffffu, ss, o);
        }
        float mean = s1 * (1.0f / HD);
        float var  = ss * (1.0f / HD) - mean * mean;
        float rstd = rsqrtf(var + LN_EPS);
        if (row < N_NODES) {
            float4 gg = *(const float4*)&g2[cc];
            float4 bb = *(const float4*)&be2[cc];
            float4 h;
            h.x = fmaxf((v.x - mean) * rstd * gg.x + bb.x, 0.f);
            h.y = fmaxf((v.y - mean) * rstd * gg.y + bb.y, 0.f);
            h.z = fmaxf((v.z - mean) * rstd * gg.z + bb.z, 0.f);
            h.w = fmaxf((v.w - mean) * rstd * gg.w + bb.w, 0.f);
            *(float4*)(g_H + row * HD + cc) = h;
        }
    }
}

// ---------------------------------------------------------------------------
// Edge kernel: one warp per UNDIRECTED edge; both directions. Half inputs.
// ---------------------------------------------------------------------------
__global__ __launch_bounds__(256) void edge_kernel(
    const int* __restrict__ eidx,
    const float* __restrict__ g1, const float* __restrict__ be1)
{
    const int wid = threadIdx.x >> 5, lane = threadIdx.x & 31;
    const long e = (long)blockIdx.x * 8 + wid;
    const int s = eidx[e], t = eidx[E_EDGES + e];

    const __half* rowS = g_PQh + (size_t)s * 256;
    const __half* rowT = g_PQh + (size_t)t * 256;
    float4 ps = ld_half4(rowS + lane * 4);
    float4 qs = ld_half4(rowS + 128 + lane * 4);
    float4 pt = ld_half4(rowT + lane * 4);
    float4 qt = ld_half4(rowT + 128 + lane * 4);
    float4 r  = ld_half4(g_Rh + (size_t)e * HD + lane * 4);
    float4 gg = *(const float4*)&g1[lane * 4];
    float4 bb = *(const float4*)&be1[lane * 4];

    float4 vf = make_float4(ps.x + qt.x + r.x, ps.y + qt.y + r.y,
                            ps.z + qt.z + r.z, ps.w + qt.w + r.w);
    float4 vb = make_float4(pt.x + qs.x + r.x, pt.y + qs.y + r.y,
                            pt.z + qs.z + r.z, pt.w + qs.w + r.w);

    float s1f = vf.x + vf.y + vf.z + vf.w;
    float ssf = vf.x * vf.x + vf.y * vf.y + vf.z * vf.z + vf.w * vf.w;
    float s1b = vb.x + vb.y + vb.z + vb.w;
    float ssb = vb.x * vb.x + vb.y * vb.y + vb.z * vb.z + vb.w * vb.w;
    #pragma unroll
    for (int o = 16; o >= 1; o >>= 1) {
        s1f += __shfl_xor_sync(0xffffffffu, s1f, o);
        ssf += __shfl_xor_sync(0xffffffffu, ssf, o);
        s1b += __shfl_xor_sync(0xffffffffu, s1b, o);
        ssb += __shfl_xor_sync(0xffffffffu, ssb, o);
    }
    {
        float mean = s1f * (1.0f / HD);
        float var  = ssf * (1.0f / HD) - mean * mean;
        float rstd = rsqrtf(var + LN_EPS);
        float h0 = fmaxf((vf.x - mean) * rstd * gg.x + bb.x, 0.f);
        float h1 = fmaxf((vf.y - mean) * rstd * gg.y + bb.y, 0.f);
        float h2 = fmaxf((vf.z - mean) * rstd * gg.z + bb.z, 0.f);
        float h3 = fmaxf((vf.w - mean) * rstd * gg.w + bb.w, 0.f);
        red_add_v4(g_hagg + (long)t * HD + lane * 4, h0, h1, h2, h3);
    }
    {
        float mean = s1b * (1.0f / HD);
        float var  = ssb * (1.0f / HD) - mean * mean;
        float rstd = rsqrtf(var + LN_EPS);
        float h0 = fmaxf((vb.x - mean) * rstd * gg.x + bb.x, 0.f);
        float h1 = fmaxf((vb.y - mean) * rstd * gg.y + bb.y, 0.f);
        float h2 = fmaxf((vb.z - mean) * rstd * gg.z + bb.z, 0.f);
        float h3 = fmaxf((vb.w - mean) * rstd * gg.w + bb.w, 0.f);
        red_add_v4(g_hagg + (long)s * HD + lane * 4, h0, h1, h2, h3);
    }
    if (lane == 0) { red_add_f32(g_deg + t, 1.0f); red_add_f32(g_deg + s, 1.0f); }
}

extern "C" void kernel_launch(void* const* d_in, const int* in_sizes, int n_in,
                              void* d_out, int out_size)
{
    const float* nf   = (const float*)d_in[0];
    const float* ef   = (const float*)d_in[1];
    const int*   eidx = (const int*)  d_in[2];
    const float* w1   = (const float*)d_in[3];
    const float* b1   = (const float*)d_in[4];
    const float* g1   = (const float*)d_in[5];
    const float* be1  = (const float*)d_in[6];
    const float* w2   = (const float*)d_in[7];
    const float* b2   = (const float*)d_in[8];
    const float* uw1  = (const float*)d_in[9];
    const float* ub1  = (const float*)d_in[10];
    const float* g2   = (const float*)d_in[11];
    const float* be2  = (const float*)d_in[12];
    const float* uw2  = (const float*)d_in[13];
    const float* ub2  = (const float*)d_in[14];
    float* out = (float*)d_out;

    float *dH;
    __half *dPQ, *dR;
    cudaGetSymbolAddress((void**)&dH,  g_H);
    cudaGetSymbolAddress((void**)&dPQ, g_PQh);
    cudaGetSymbolAddress((void**)&dR,  g_Rh);

    const int gN = (N_NODES + 63) / 64;   // 1563
    const int gE = (E_EDGES + 63) / 64;   // 6250

    zero_kernel<<<592, 256>>>();
    d2_kernel<<<1, 128>>>(uw1, b2);
    split_all_kernel<<<(N_SPLIT_IN + 255) / 256, 256>>>(w1, uw1, uw2);
    w2p_kernel<<<128, 128>>>(w2, uw1);
    // P (cols 0:128 of PQ), Q (cols 128:256), R (half outputs)
    gemm_tc<<<gN, 256>>>(nf, N_NODES, ND, OFF_W1, nullptr, nullptr, nullptr, dPQ, 256, 0);
    gemm_tc<<<gN, 256>>>(nf, N_NODES, ND, OFF_W1 + ND * HD, nullptr, nullptr, nullptr, dPQ, 256, 128);
    gemm_tc<<<gE, 256>>>(ef, E_EDGES, ED, OFF_W1 + 2 * ND * HD, b1, nullptr, nullptr, dR, 128, 0);
    // edges: gather + LN + scatter
    edge_kernel<<<E_EDGES / 8, 256>>>(eidx, g1, be1);
    // fused update MLP layer-1 + LN
    upd_fused<<<gN, 256>>>(nf, ub1, g2, be2);
    // out = H@uw2 + ub2 + nf  (float path)
    gemm_tc<<<gN, 256>>>(dH, N_NODES, HD, OFF_UW2, ub2, nf, out, nullptr, 0, 0);
}

// round 11
// speedup vs baseline: 1.4097x; 1.0121x over previous
#include <cuda_runtime.h>
#include <cuda_fp16.h>
#include <math.h>
#include <stdint.h>

#define N_NODES 100000
#define E_EDGES 400000
#define ND 128
#define ED 64
#define HD 128
#define LN_EPS 1e-5f

// Scratch (__device__ globals: allocation-free rule)
__device__ float  g_hagg[(size_t)N_NODES * HD];
__device__ float  g_deg[N_NODES];
__device__ __half g_PQh[(size_t)N_NODES * 256];   // [node][0:128]=P, [128:256]=Q
__device__ float  g_H[(size_t)N_NODES * HD];
__device__ float  g_d2[HD];

// Pre-split weight planes (hi/lo TF32). Flat layout:
//   w1  @ 0       (320*128 = 40960)  [W1c rows at 256*128 = 32768]
//   uw1 @ 40960   (256*128 = 32768)
//   uw2 @ 73728   (128*128 = 16384)
//   W2p @ 90112   (128*128 = 16384)
#define OFF_W1   0
#define OFF_W1C  32768
#define OFF_UW1  40960
#define OFF_UW2  73728
#define OFF_W2P  90112
#define N_SPLIT_IN 90112
__device__ float g_Whi[106496];
__device__ float g_Wlo[106496];

// ---------------- helpers ----------------
__device__ __forceinline__ void red_add_v4(float* p, float a, float b, float c, float d) {
    asm volatile("red.global.add.v4.f32 [%0], {%1, %2, %3, %4};"
                 :: "l"(p), "f"(a), "f"(b), "f"(c), "f"(d) : "memory");
}
__device__ __forceinline__ void red_add_f32(float* p, float v) {
    asm volatile("red.global.add.f32 [%0], %1;" :: "l"(p), "f"(v) : "memory");
}
__device__ __forceinline__ float2 split_f(float x) {
    uint32_t hi;
    asm("cvt.rna.tf32.f32 %0, %1;" : "=r"(hi) : "f"(x));
    float h = __uint_as_float(hi);
    float r = x - h;
    uint32_t lo;
    asm("cvt.rna.tf32.f32 %0, %1;" : "=r"(lo) : "f"(r));
    return make_float2(h, __uint_as_float(lo));
}
__device__ __forceinline__ void mma_tf32(float d[4], const uint32_t a[4], const uint32_t b[2]) {
    asm("mma.sync.aligned.m16n8k8.row.col.f32.tf32.tf32.f32 "
        "{%0,%1,%2,%3}, {%4,%5,%6,%7}, {%8,%9}, {%0,%1,%2,%3};"
        : "+f"(d[0]), "+f"(d[1]), "+f"(d[2]), "+f"(d[3])
        : "r"(a[0]), "r"(a[1]), "r"(a[2]), "r"(a[3]), "r"(b[0]), "r"(b[1]));
}
__device__ __forceinline__ void cp_async16(void* smem, const void* gmem) {
    uint32_t s = (uint32_t)__cvta_generic_to_shared(smem);
    asm volatile("cp.async.cg.shared.global [%0], [%1], 16;" :: "r"(s), "l"(gmem));
}
#define CP_COMMIT() asm volatile("cp.async.commit_group;")
#define CP_WAIT1()  asm volatile("cp.async.wait_group 1;")

__device__ __forceinline__ float4 ld_half4(const __half* p) {
    uint2 u = *(const uint2*)p;
    __half2 a = *reinterpret_cast<__half2*>(&u.x);
    __half2 b = *reinterpret_cast<__half2*>(&u.y);
    float2 fa = __half22float2(a), fb = __half22float2(b);
    return make_float4(fa.x, fa.y, fb.x, fb.y);
}

__global__ void zero_kernel() {
    float4* p = reinterpret_cast<float4*>(g_hagg);
    const int n4 = N_NODES * HD / 4;
    for (int i = blockIdx.x * blockDim.x + threadIdx.x; i < n4;
         i += gridDim.x * blockDim.x)
        p[i] = make_float4(0.f, 0.f, 0.f, 0.f);
    for (int i = blockIdx.x * blockDim.x + threadIdx.x; i < N_NODES;
         i += gridDim.x * blockDim.x)
        g_deg[i] = 0.f;
}

// Split w1, uw1, uw2 into hi/lo planes in one launch.
__global__ void split_all_kernel(const float* __restrict__ w1,
                                 const float* __restrict__ uw1,
                                 const float* __restrict__ uw2)
{
    int i = blockIdx.x * blockDim.x + threadIdx.x;
    if (i >= N_SPLIT_IN) return;
    float v;
    if (i < OFF_UW1)       v = w1[i];
    else if (i < OFF_UW2)  v = uw1[i - OFF_UW1];
    else                   v = uw2[i - OFF_UW2];
    float2 s = split_f(v);
    g_Whi[i] = s.x;
    g_Wlo[i] = s.y;
}

// W2p = W2 @ uw1b computed + split; block 128 computes d2 = b2 @ uw1b.
__global__ void w2p_kernel(const float* __restrict__ w2,
                           const float* __restrict__ uw1,
                           const float* __restrict__ b2) {
    int n = threadIdx.x;
    if (blockIdx.x == 128) {
        float s = 0.f;
        for (int k = 0; k < HD; k++)
            s = fmaf(b2[k], uw1[(ND + k) * HD + n], s);
        g_d2[n] = s;
        return;
    }
    int k = blockIdx.x;
    float s = 0.f;
    for (int m = 0; m < HD; m++)
        s = fmaf(w2[k * HD + m], uw1[(ND + m) * HD + n], s);
    float2 sp = split_f(s);
    g_Whi[OFF_W2P + k * HD + n] = sp.x;
    g_Wlo[OFF_W2P + k * HD + n] = sp.y;
}

// ---------------------------------------------------------------------------
// gemm_tc: D = A[M][K] @ W[K][128] (+bias).  Output: half (Ch,ldc,colOff) or
// float C (+resid). 3xTF32; A split at fragment load; W pre-split; cp.async x2.
// ---------------------------------------------------------------------------
__global__ __launch_bounds__(256, 2) void gemm_tc(
    const float* __restrict__ A, int M, int K,
    int wOff, const float* __restrict__ bias,
    const float* __restrict__ resid, float* __restrict__ C,
    __half* __restrict__ Ch, int ldc, int colOff)
{
    __shared__ float As[2][64][20];
    __shared__ float Whs[2][16][136];
    __shared__ float Wls[2][16][136];

    const float* Whi = g_Whi + wOff;
    const float* Wlo = g_Wlo + wOff;

    const int tid = threadIdx.x;
    const int lane = tid & 31, warp = tid >> 5;
    const int wm = warp >> 2, wn = warp & 3;
    const int g = lane >> 2, tig = lane & 3;
    const long rBase = (long)blockIdx.x * 64;

    const int arow = tid >> 2, akq = tid & 3;
    long gArow = rBase + arow; if (gArow >= M) gArow = M - 1;
    const int wkr = tid >> 5, wcc = tid & 31;

    const int nChunks = K >> 4;

    float d[2][4][4];
    #pragma unroll
    for (int mf = 0; mf < 2; mf++)
        #pragma unroll
        for (int nf = 0; nf < 4; nf++)
            #pragma unroll
            for (int q = 0; q < 4; q++) d[mf][nf][q] = 0.f;

    cp_async16(&As[0][arow][akq * 4], A + gArow * K + akq * 4);
    cp_async16(&Whs[0][wkr][wcc * 4],     Whi + (long)wkr * 128 + wcc * 4);
    cp_async16(&Whs[0][wkr + 8][wcc * 4], Whi + (long)(wkr + 8) * 128 + wcc * 4);
    cp_async16(&Wls[0][wkr][wcc * 4],     Wlo + (long)wkr * 128 + wcc * 4);
    cp_async16(&Wls[0][wkr + 8][wcc * 4], Wlo + (long)(wkr + 8) * 128 + wcc * 4);
    CP_COMMIT();

    for (int c = 0; c < nChunks; c++) {
        if (c + 1 < nChunks) {
            int kc = (c + 1) * 16, buf = (c + 1) & 1;
            cp_async16(&As[buf][arow][akq * 4], A + gArow * K + kc + akq * 4);
            cp_async16(&Whs[buf][wkr][wcc * 4],     Whi + (long)(kc + wkr) * 128 + wcc * 4);
            cp_async16(&Whs[buf][wkr + 8][wcc * 4], Whi + (long)(kc + 8 + wkr) * 128 + wcc * 4);
            cp_async16(&Wls[buf][wkr][wcc * 4],     Wlo + (long)(kc + wkr) * 128 + wcc * 4);
            cp_async16(&Wls[buf][wkr + 8][wcc * 4], Wlo + (long)(kc + 8 + wkr) * 128 + wcc * 4);
        }
        CP_COMMIT();
        CP_WAIT1();
        __syncthreads();
        const int buf = c & 1;
        #pragma unroll
        for (int k8 = 0; k8 < 16; k8 += 8) {
            uint32_t ahi[2][4], alo[2][4], bhi[4][2], blo[4][2];
            #pragma unroll
            for (int mf = 0; mf < 2; mf++) {
                int mb = wm * 32 + mf * 16;
                float2 s0 = split_f(As[buf][mb + g][k8 + tig]);
                float2 s1 = split_f(As[buf][mb + 8 + g][k8 + tig]);
                float2 s2 = split_f(As[buf][mb + g][k8 + tig + 4]);
                float2 s3 = split_f(As[buf][mb + 8 + g][k8 + tig + 4]);
                ahi[mf][0] = __float_as_uint(s0.x); alo[mf][0] = __float_as_uint(s0.y);
                ahi[mf][1] = __float_as_uint(s1.x); alo[mf][1] = __float_as_uint(s1.y);
                ahi[mf][2] = __float_as_uint(s2.x); alo[mf][2] = __float_as_uint(s2.y);
                ahi[mf][3] = __float_as_uint(s3.x); alo[mf][3] = __float_as_uint(s3.y);
            }
            #pragma unroll
            for (int nf = 0; nf < 4; nf++) {
                int nb = wn * 32 + nf * 8;
                bhi[nf][0] = __float_as_uint(Whs[buf][k8 + tig][nb + g]);
                bhi[nf][1] = __float_as_uint(Whs[buf][k8 + tig + 4][nb + g]);
                blo[nf][0] = __float_as_uint(Wls[buf][k8 + tig][nb + g]);
                blo[nf][1] = __float_as_uint(Wls[buf][k8 + tig + 4][nb + g]);
            }
            #pragma unroll
            for (int mf = 0; mf < 2; mf++)
                #pragma unroll
                for (int nf = 0; nf < 4; nf++) {
                    mma_tf32(d[mf][nf], ahi[mf], bhi[nf]);
                    mma_tf32(d[mf][nf], alo[mf], bhi[nf]);
                    mma_tf32(d[mf][nf], ahi[mf], blo[nf]);
                }
        }
        __syncthreads();
    }

    #pragma unroll
    for (int mf = 0; mf < 2; mf++) {
        #pragma unroll
        for (int r2 = 0; r2 < 2; r2++) {
            long m = rBase + wm * 32 + mf * 16 + g + r2 * 8;
            if (m < M) {
                #pragma unroll
                for (int nf = 0; nf < 4; nf++) {
                    int n = wn * 32 + nf * 8 + 2 * tig;
                    float v0 = d[mf][nf][r2 * 2];
                    float v1 = d[mf][nf][r2 * 2 + 1];
                    if (bias) { v0 += bias[n]; v1 += bias[n + 1]; }
                    if (Ch) {
                        *(__half2*)(Ch + m * ldc + colOff + n) = __floats2half2_rn(v0, v1);
                    } else {
                        if (resid) { float2 rr = *(const float2*)(resid + m * 128 + n);
                                     v0 += rr.x; v1 += rr.y; }
                        *(float2*)(C + m * 128 + n) = make_float2(v0, v1);
                    }
                }
            }
        }
    }
}

// ---------------------------------------------------------------------------
// msg_fused: per CTA, 64 undirected edges.
//   R tile = ef[eBase:eBase+64] @ W1c + b1    (tensor-core mainloop, K=64)
//   staged in SMEM, then warp-per-edge:
//   fwd h=relu(LN(P[s]+Q[t]+R)) -> hagg[t]; bwd h=relu(LN(P[t]+Q[s]+R)) -> hagg[s]
// ---------------------------------------------------------------------------
__global__ __launch_bounds__(256, 2) void msg_fused(
    const float* __restrict__ ef, const int* __restrict__ eidx,
    const float* __restrict__ b1,
    const float* __restrict__ g1, const float* __restrict__ be1)
{
    __shared__ float pool[11264];
    #define ASP(b, r, c)  pool[(b) * 1280 + (r) * 20 + (c)]
    #define WHSP(b, r, c) pool[2560 + (b) * 2176 + (r) * 136 + (c)]
    #define WLSP(b, r, c) pool[6912 + (b) * 2176 + (r) * 136 + (c)]
    #define CSP(r, c)     pool[(r) * 132 + (c)]
    __shared__ int sS[64], sT[64];

    const float* Whi = g_Whi + OFF_W1C;
    const float* Wlo = g_Wlo + OFF_W1C;

    const int tid = threadIdx.x;
    const int lane = tid & 31, warp = tid >> 5;
    const int wm = warp >> 2, wn = warp & 3;
    const int g = lane >> 2, tig = lane & 3;
    const long eBase = (long)blockIdx.x * 64;   // grid is exact: 400000/64 = 6250

    if (tid < 64) {
        sS[tid] = eidx[eBase + tid];
        sT[tid] = eidx[E_EDGES + eBase + tid];
    }

    const int arow = tid >> 2, akq = tid & 3;
    const long gArow = eBase + arow;
    const int wkr = tid >> 5, wcc = tid & 31;

    float d[2][4][4];
    #pragma unroll
    for (int mf = 0; mf < 2; mf++)
        #pragma unroll
        for (int nf = 0; nf < 4; nf++)
            #pragma unroll
            for (int q = 0; q < 4; q++) d[mf][nf][q] = 0.f;

    cp_async16(&ASP(0, arow, akq * 4), ef + gArow * ED + akq * 4);
    cp_async16(&WHSP(0, wkr, wcc * 4),     Whi + (long)wkr * 128 + wcc * 4);
    cp_async16(&WHSP(0, wkr + 8, wcc * 4), Whi + (long)(wkr + 8) * 128 + wcc * 4);
    cp_async16(&WLSP(0, wkr, wcc * 4),     Wlo + (long)wkr * 128 + wcc * 4);
    cp_async16(&WLSP(0, wkr + 8, wcc * 4), Wlo + (long)(wkr + 8) * 128 + wcc * 4);
    CP_COMMIT();

    for (int c = 0; c < 4; c++) {           // K = ED = 64 -> 4 chunks
        if (c + 1 < 4) {
            int kc = (c + 1) * 16, buf = (c + 1) & 1;
            cp_async16(&ASP(buf, arow, akq * 4), ef + gArow * ED + kc + akq * 4);
            cp_async16(&WHSP(buf, wkr, wcc * 4),     Whi + (long)(kc + wkr) * 128 + wcc * 4);
            cp_async16(&WHSP(buf, wkr + 8, wcc * 4), Whi + (long)(kc + 8 + wkr) * 128 + wcc * 4);
            cp_async16(&WLSP(buf, wkr, wcc * 4),     Wlo + (long)(kc + wkr) * 128 + wcc * 4);
            cp_async16(&WLSP(buf, wkr + 8, wcc * 4), Wlo + (long)(kc + 8 + wkr) * 128 + wcc * 4);
        }
        CP_COMMIT();
        CP_WAIT1();
        __syncthreads();
        const int buf = c & 1;
        #pragma unroll
        for (int k8 = 0; k8 < 16; k8 += 8) {
            uint32_t ahi[2][4], alo[2][4], bhi[4][2], blo[4][2];
            #pragma unroll
            for (int mf = 0; mf < 2; mf++) {
                int mb = wm * 32 + mf * 16;
                float2 s0 = split_f(ASP(buf, mb + g, k8 + tig));
                float2 s1 = split_f(ASP(buf, mb + 8 + g, k8 + tig));
                float2 s2 = split_f(ASP(buf, mb + g, k8 + tig + 4));
                float2 s3 = split_f(ASP(buf, mb + 8 + g, k8 + tig + 4));
                ahi[mf][0] = __float_as_uint(s0.x); alo[mf][0] = __float_as_uint(s0.y);
                ahi[mf][1] = __float_as_uint(s1.x); alo[mf][1] = __float_as_uint(s1.y);
                ahi[mf][2] = __float_as_uint(s2.x); alo[mf][2] = __float_as_uint(s2.y);
                ahi[mf][3] = __float_as_uint(s3.x); alo[mf][3] = __float_as_uint(s3.y);
            }
            #pragma unroll
            for (int nf2 = 0; nf2 < 4; nf2++) {
                int nb = wn * 32 + nf2 * 8;
                bhi[nf2][0] = __float_as_uint(WHSP(buf, k8 + tig, nb + g));
                bhi[nf2][1] = __float_as_uint(WHSP(buf, k8 + tig + 4, nb + g));
                blo[nf2][0] = __float_as_uint(WLSP(buf, k8 + tig, nb + g));
                blo[nf2][1] = __float_as_uint(WLSP(buf, k8 + tig + 4, nb + g));
            }
            #pragma unroll
            for (int mf = 0; mf < 2; mf++)
                #pragma unroll
                for (int nf2 = 0; nf2 < 4; nf2++) {
                    mma_tf32(d[mf][nf2], ahi[mf], bhi[nf2]);
                    mma_tf32(d[mf][nf2], alo[mf], bhi[nf2]);
                    mma_tf32(d[mf][nf2], ahi[mf], blo[nf2]);
                }
        }
        __syncthreads();
    }

    // stage R tile (+b1) into SMEM (aliases compute buffers; loop done)
    #pragma unroll
    for (int mf = 0; mf < 2; mf++)
        #pragma unroll
        for (int r2 = 0; r2 < 2; r2++) {
            int lr = wm * 32 + mf * 16 + g + r2 * 8;
            #pragma unroll
            for (int nf2 = 0; nf2 < 4; nf2++) {
                int n = wn * 32 + nf2 * 8 + 2 * tig;
                CSP(lr, n)     = d[mf][nf2][r2 * 2]     + b1[n];
                CSP(lr, n + 1) = d[mf][nf2][r2 * 2 + 1] + b1[n + 1];
            }
        }
    __syncthreads();

    // edge phase: warp-per-edge, 8 edges per warp
    float4 gg = *(const float4*)&g1[lane * 4];
    float4 bb = *(const float4*)&be1[lane * 4];
    #pragma unroll
    for (int r8 = 0; r8 < 8; r8++) {
        int lr = warp * 8 + r8;
        int s = sS[lr], t = sT[lr];
        const __half* rowS = g_PQh + (size_t)s * 256;
        const __half* rowT = g_PQh + (size_t)t * 256;
        float4 ps = ld_half4(rowS + lane * 4);
        float4 qs = ld_half4(rowS + 128 + lane * 4);
        float4 pt = ld_half4(rowT + lane * 4);
        float4 qt = ld_half4(rowT + 128 + lane * 4);
        float4 r  = *(float4*)&CSP(lr, lane * 4);

        float4 vf = make_float4(ps.x + qt.x + r.x, ps.y + qt.y + r.y,
                                ps.z + qt.z + r.z, ps.w + qt.w + r.w);
        float4 vb = make_float4(pt.x + qs.x + r.x, pt.y + qs.y + r.y,
                                pt.z + qs.z + r.z, pt.w + qs.w + r.w);

        float s1f = vf.x + vf.y + vf.z + vf.w;
        float ssf = vf.x * vf.x + vf.y * vf.y + vf.z * vf.z + vf.w * vf.w;
        float s1b = vb.x + vb.y + vb.z + vb.w;
        float ssb = vb.x * vb.x + vb.y * vb.y + vb.z * vb.z + vb.w * vb.w;
        #pragma unroll
        for (int o = 16; o >= 1; o >>= 1) {
            s1f += __shfl_xor_sync(0xffffffffu, s1f, o);
            ssf += __shfl_xor_sync(0xffffffffu, ssf, o);
            s1b += __shfl_xor_sync(0xffffffffu, s1b, o);
            ssb += __shfl_xor_sync(0xffffffffu, ssb, o);
        }
        {
            float mean = s1f * (1.0f / HD);
            float var  = ssf * (1.0f / HD) - mean * mean;
            float rstd = rsqrtf(var + LN_EPS);
            float h0 = fmaxf((vf.x - mean) * rstd * gg.x + bb.x, 0.f);
            float h1 = fmaxf((vf.y - mean) * rstd * gg.y + bb.y, 0.f);
            float h2 = fmaxf((vf.z - mean) * rstd * gg.z + bb.z, 0.f);
            float h3 = fmaxf((vf.w - mean) * rstd * gg.w + bb.w, 0.f);
            red_add_v4(g_hagg + (long)t * HD + lane * 4, h0, h1, h2, h3);
        }
        {
            float mean = s1b * (1.0f / HD);
            float var  = ssb * (1.0f / HD) - mean * mean;
            float rstd = rsqrtf(var + LN_EPS);
            float h0 = fmaxf((vb.x - mean) * rstd * gg.x + bb.x, 0.f);
            float h1 = fmaxf((vb.y - mean) * rstd * gg.y + bb.y, 0.f);
            float h2 = fmaxf((vb.z - mean) * rstd * gg.z + bb.z, 0.f);
            float h3 = fmaxf((vb.w - mean) * rstd * gg.w + bb.w, 0.f);
            red_add_v4(g_hagg + (long)s * HD + lane * 4, h0, h1, h2, h3);
        }
        if (lane == 0) { red_add_f32(g_deg + t, 1.0f); red_add_f32(g_deg + s, 1.0f); }
    }
}

// ---------------------------------------------------------------------------
// upd_fused: g_H = relu(LN(nf@uw1a + hagg@W2p + ub1 + deg*d2) * g2 + be2)
// ---------------------------------------------------------------------------
__global__ __launch_bounds__(256, 2) void upd_fused(
    const float* __restrict__ nf, const float* __restrict__ ub1,
    const float* __restrict__ g2, const float* __restrict__ be2)
{
    __shared__ float pool[11264];

    const float* haggp = g_hagg;
    const int tid = threadIdx.x;
    const int lane = tid & 31, warp = tid >> 5;
    const int wm = warp >> 2, wn = warp & 3;
    const int g = lane >> 2, tig = lane & 3;
    const long rBase = (long)blockIdx.x * 64;

    const int arow = tid >> 2, akq = tid & 3;
    long gArow = rBase + arow; if (gArow >= N_NODES) gArow = N_NODES - 1;
    const int wkr = tid >> 5, wcc = tid & 31;

    float d[2][4][4];
    #pragma unroll
    for (int mf = 0; mf < 2; mf++)
        #pragma unroll
        for (int nf = 0; nf < 4; nf++)
            #pragma unroll
            for (int q = 0; q < 4; q++) d[mf][nf][q] = 0.f;

    {
        const float* Wh0 = g_Whi + OFF_UW1;
        const float* Wl0 = g_Wlo + OFF_UW1;
        cp_async16(&ASP(0, arow, akq * 4), nf + gArow * HD + akq * 4);
        cp_async16(&WHSP(0, wkr, wcc * 4),     Wh0 + (long)wkr * 128 + wcc * 4);
        cp_async16(&WHSP(0, wkr + 8, wcc * 4), Wh0 + (long)(wkr + 8) * 128 + wcc * 4);
        cp_async16(&WLSP(0, wkr, wcc * 4),     Wl0 + (long)wkr * 128 + wcc * 4);
        cp_async16(&WLSP(0, wkr + 8, wcc * 4), Wl0 + (long)(wkr + 8) * 128 + wcc * 4);
        CP_COMMIT();
    }

    for (int c = 0; c < 16; c++) {
        if (c + 1 < 16) {
            int cn = c + 1, buf = cn & 1;
            int kc = (cn & 7) * 16;
            const float* An  = (cn < 8) ? nf : haggp;
            const float* Whn = g_Whi + ((cn < 8) ? OFF_UW1 : OFF_W2P);
            const float* Wln = g_Wlo + ((cn < 8) ? OFF_UW1 : OFF_W2P);
            cp_async16(&ASP(buf, arow, akq * 4), An + gArow * HD + kc + akq * 4);
            cp_async16(&WHSP(buf, wkr, wcc * 4),     Whn + (long)(kc + wkr) * 128 + wcc * 4);
            cp_async16(&WHSP(buf, wkr + 8, wcc * 4), Whn + (long)(kc + 8 + wkr) * 128 + wcc * 4);
            cp_async16(&WLSP(buf, wkr, wcc * 4),     Wln + (long)(kc + wkr) * 128 + wcc * 4);
            cp_async16(&WLSP(buf, wkr + 8, wcc * 4), Wln + (long)(kc + 8 + wkr) * 128 + wcc * 4);
        }
        CP_COMMIT();
        CP_WAIT1();
        __syncthreads();
        const int buf = c & 1;
        #pragma unroll
        for (int k8 = 0; k8 < 16; k8 += 8) {
            uint32_t ahi[2][4], alo[2][4], bhi[4][2], blo[4][2];
            #pragma unroll
            for (int mf = 0; mf < 2; mf++) {
                int mb = wm * 32 + mf * 16;
                float2 s0 = split_f(ASP(buf, mb + g, k8 + tig));
                float2 s1 = split_f(ASP(buf, mb + 8 + g, k8 + tig));
                float2 s2 = split_f(ASP(buf, mb + g, k8 + tig + 4));
                float2 s3 = split_f(ASP(buf, mb + 8 + g, k8 + tig + 4));
                ahi[mf][0] = __float_as_uint(s0.x); alo[mf][0] = __float_as_uint(s0.y);
                ahi[mf][1] = __float_as_uint(s1.x); alo[mf][1] = __float_as_uint(s1.y);
                ahi[mf][2] = __float_as_uint(s2.x); alo[mf][2] = __float_as_uint(s2.y);
                ahi[mf][3] = __float_as_uint(s3.x); alo[mf][3] = __float_as_uint(s3.y);
            }
            #pragma unroll
            for (int nf2 = 0; nf2 < 4; nf2++) {
                int nb = wn * 32 + nf2 * 8;
                bhi[nf2][0] = __float_as_uint(WHSP(buf, k8 + tig, nb + g));
                bhi[nf2][1] = __float_as_uint(WHSP(buf, k8 + tig + 4, nb + g));
                blo[nf2][0] = __float_as_uint(WLSP(buf, k8 + tig, nb + g));
                blo[nf2][1] = __float_as_uint(WLSP(buf, k8 + tig + 4, nb + g));
            }
            #pragma unroll
            for (int mf = 0; mf < 2; mf++)
                #pragma unroll
                for (int nf2 = 0; nf2 < 4; nf2++) {
                    mma_tf32(d[mf][nf2], ahi[mf], bhi[nf2]);
                    mma_tf32(d[mf][nf2], alo[mf], bhi[nf2]);
                    mma_tf32(d[mf][nf2], ahi[mf], blo[nf2]);
                }
        }
        __syncthreads();
    }

    #pragma unroll
    for (int mf = 0; mf < 2; mf++)
        #pragma unroll
        for (int r2 = 0; r2 < 2; r2++) {
            int lr = wm * 32 + mf * 16 + g + r2 * 8;
            #pragma unroll
            for (int nf2 = 0; nf2 < 4; nf2++) {
                int n = wn * 32 + nf2 * 8 + 2 * tig;
                CSP(lr, n)     = d[mf][nf2][r2 * 2];
                CSP(lr, n + 1) = d[mf][nf2][r2 * 2 + 1];
            }
        }
    __syncthreads();

    #pragma unroll
    for (int r8 = 0; r8 < 8; r8++) {
        int lr = warp * 8 + r8;
        long row = rBase + lr;
        long rowc = row < N_NODES ? row : N_NODES - 1;
        float dg = g_deg[rowc];
        int cc = lane * 4;
        float4 v = *(float4*)&CSP(lr, cc);
        float4 ub = *(const float4*)&ub1[cc];
        float4 dd = *(const float4*)&g_d2[cc];
        v.x += ub.x + dg * dd.x; v.y += ub.y + dg * dd.y;
        v.z += ub.z + dg * dd.z; v.w += ub.w + dg * dd.w;
        float s1 = v.x + v.y + v.z + v.w;
        float ss = v.x * v.x + v.y * v.y + v.z * v.z + v.w * v.w;
        #pragma unroll
        for (int o = 16; o >= 1; o >>= 1) {
            s1 += __shfl_xor_sync(0xffffffffu, s1, o);
            ss += __shfl_xor_sync(0xffffffffu, ss, o);
        }
        float mean = s1 * (1.0f / HD);
        float var  = ss * (1.0f / HD) - mean * mean;
        float rstd = rsqrtf(var + LN_EPS);
        if (row < N_NODES) {
            float4 gg = *(const float4*)&g2[cc];
            float4 bb = *(const float4*)&be2[cc];
            float4 h;
            h.x = fmaxf((v.x - mean) * rstd * gg.x + bb.x, 0.f);
            h.y = fmaxf((v.y - mean) * rstd * gg.y + bb.y, 0.f);
            h.z = fmaxf((v.z - mean) * rstd * gg.z + bb.z, 0.f);
            h.w = fmaxf((v.w - mean) * rstd * gg.w + bb.w, 0.f);
            *(float4*)(g_H + row * HD + cc) = h;
        }
    }
}

extern "C" void kernel_launch(void* const* d_in, const int* in_sizes, int n_in,
                              void* d_out, int out_size)
{
    const float* nf   = (const float*)d_in[0];
    const float* ef   = (const float*)d_in[1];
    const int*   eidx = (const int*)  d_in[2];
    const float* w1   = (const float*)d_in[3];
    const float* b1   = (const float*)d_in[4];
    const float* g1   = (const float*)d_in[5];
    const float* be1  = (const float*)d_in[6];
    const float* w2   = (const float*)d_in[7];
    const float* b2   = (const float*)d_in[8];
    const float* uw1  = (const float*)d_in[9];
    const float* ub1  = (const float*)d_in[10];
    const float* g2   = (const float*)d_in[11];
    const float* be2  = (const float*)d_in[12];
    const float* uw2  = (const float*)d_in[13];
    const float* ub2  = (const float*)d_in[14];
    float* out = (float*)d_out;

    float *dH;
    __half *dPQ;
    cudaGetSymbolAddress((void**)&dH,  g_H);
    cudaGetSymbolAddress((void**)&dPQ, g_PQh);

    const int gN = (N_NODES + 63) / 64;   // 1563
    const int gE = E_EDGES / 64;          // 6250 (exact)

    zero_kernel<<<592, 256>>>();
    split_all_kernel<<<(N_SPLIT_IN + 255) / 256, 256>>>(w1, uw1, uw2);
    w2p_kernel<<<129, 128>>>(w2, uw1, b2);
    // P (cols 0:128 of PQ), Q (cols 128:256)
    gemm_tc<<<gN, 256>>>(nf, N_NODES, ND, OFF_W1, nullptr, nullptr, nullptr, dPQ, 256, 0);
    gemm_tc<<<gN, 256>>>(nf, N_NODES, ND, OFF_W1 + ND * HD, nullptr, nullptr, nullptr, dPQ, 256, 128);
    // fused message: R-gemm + gather + LN + scatter
    msg_fused<<<gE, 256>>>(ef, eidx, b1, g1, be1);
    // fused update MLP layer-1 + LN
    upd_fused<<<gN, 256>>>(nf, ub1, g2, be2);
    // out = H@uw2 + ub2 + nf
    gemm_tc<<<gN, 256>>>(dH, N_NODES, HD, OFF_UW2, ub2, nf, out, nullptr, 0, 0);
}

// round 12
// speedup vs baseline: 1.4489x; 1.0278x over previous
#include <cuda_runtime.h>
#include <cuda_fp16.h>
#include <math.h>
#include <stdint.h>

#define N_NODES 100000
#define E_EDGES 400000
#define ND 128
#define ED 64
#define HD 128
#define LN_EPS 1e-5f

// Scratch (__device__ globals: allocation-free rule)
__device__ __half g_hagg_h[(size_t)N_NODES * HD];  // fp16 atomic accumulator
__device__ float  g_deg[N_NODES];
__device__ __half g_PQh[(size_t)N_NODES * 256];    // [node][0:128]=P, [128:256]=Q
__device__ float  g_d2[HD];

// Pre-split weight planes (hi/lo TF32). Flat layout:
//   w1  @ 0       (320*128 = 40960)  [W1c rows at 32768]
//   uw1 @ 40960   (256*128 = 32768)
//   uw2 @ 73728   (128*128 = 16384)
//   W2p @ 90112   (128*128 = 16384)
#define OFF_W1   0
#define OFF_W1C  32768
#define OFF_UW1  40960
#define OFF_UW2  73728
#define OFF_W2P  90112
#define N_SPLIT_IN 90112
__device__ float g_Whi[106496];
__device__ float g_Wlo[106496];

// ---------------- helpers ----------------
__device__ __forceinline__ void red_add_f32(float* p, float v) {
    asm volatile("red.global.add.f32 [%0], %1;" :: "l"(p), "f"(v) : "memory");
}
// 4 floats -> 2x f16x2 atomic adds (8B payload)
__device__ __forceinline__ void red_add_h4(__half* p, float a, float b, float c, float d) {
    __half2 v01 = __floats2half2_rn(a, b);
    __half2 v23 = __floats2half2_rn(c, d);
    uint32_t u01 = *reinterpret_cast<uint32_t*>(&v01);
    uint32_t u23 = *reinterpret_cast<uint32_t*>(&v23);
    asm volatile("red.global.add.noftz.f16x2 [%0], %1;" :: "l"(p),     "r"(u01) : "memory");
    asm volatile("red.global.add.noftz.f16x2 [%0], %1;" :: "l"(p + 2), "r"(u23) : "memory");
}
__device__ __forceinline__ float2 split_f(float x) {
    uint32_t hi;
    asm("cvt.rna.tf32.f32 %0, %1;" : "=r"(hi) : "f"(x));
    float h = __uint_as_float(hi);
    float r = x - h;
    uint32_t lo;
    asm("cvt.rna.tf32.f32 %0, %1;" : "=r"(lo) : "f"(r));
    return make_float2(h, __uint_as_float(lo));
}
__device__ __forceinline__ void mma_tf32(float d[4], const uint32_t a[4], const uint32_t b[2]) {
    asm("mma.sync.aligned.m16n8k8.row.col.f32.tf32.tf32.f32 "
        "{%0,%1,%2,%3}, {%4,%5,%6,%7}, {%8,%9}, {%0,%1,%2,%3};"
        : "+f"(d[0]), "+f"(d[1]), "+f"(d[2]), "+f"(d[3])
        : "r"(a[0]), "r"(a[1]), "r"(a[2]), "r"(a[3]), "r"(b[0]), "r"(b[1]));
}
__device__ __forceinline__ void cp_async16(void* smem, const void* gmem) {
    uint32_t s = (uint32_t)__cvta_generic_to_shared(smem);
    asm volatile("cp.async.cg.shared.global [%0], [%1], 16;" :: "r"(s), "l"(gmem));
}
__device__ __forceinline__ void cp_async8(void* smem, const void* gmem) {
    uint32_t s = (uint32_t)__cvta_generic_to_shared(smem);
    asm volatile("cp.async.ca.shared.global [%0], [%1], 8;" :: "r"(s), "l"(gmem));
}
#define CP_COMMIT() asm volatile("cp.async.commit_group;")
#define CP_WAIT1()  asm volatile("cp.async.wait_group 1;")

__device__ __forceinline__ float4 ld_half4(const __half* p) {
    uint2 u = *(const uint2*)p;
    __half2 a = *reinterpret_cast<__half2*>(&u.x);
    __half2 b = *reinterpret_cast<__half2*>(&u.y);
    float2 fa = __half22float2(a), fb = __half22float2(b);
    return make_float4(fa.x, fa.y, fb.x, fb.y);
}

__global__ void zero_kernel() {
    uint4* p = reinterpret_cast<uint4*>(g_hagg_h);
    const int n16 = (int)(((size_t)N_NODES * HD * 2) / 16);
    uint4 z = make_uint4(0, 0, 0, 0);
    for (int i = blockIdx.x * blockDim.x + threadIdx.x; i < n16;
         i += gridDim.x * blockDim.x)
        p[i] = z;
    for (int i = blockIdx.x * blockDim.x + threadIdx.x; i < N_NODES;
         i += gridDim.x * blockDim.x)
        g_deg[i] = 0.f;
}

__global__ void split_all_kernel(const float* __restrict__ w1,
                                 const float* __restrict__ uw1,
                                 const float* __restrict__ uw2)
{
    int i = blockIdx.x * blockDim.x + threadIdx.x;
    if (i >= N_SPLIT_IN) return;
    float v;
    if (i < OFF_UW1)       v = w1[i];
    else if (i < OFF_UW2)  v = uw1[i - OFF_UW1];
    else                   v = uw2[i - OFF_UW2];
    float2 s = split_f(v);
    g_Whi[i] = s.x;
    g_Wlo[i] = s.y;
}

// W2p = W2 @ uw1b (+split); block 128 computes d2 = b2 @ uw1b.
__global__ void w2p_kernel(const float* __restrict__ w2,
                           const float* __restrict__ uw1,
                           const float* __restrict__ b2) {
    int n = threadIdx.x;
    if (blockIdx.x == 128) {
        float s = 0.f;
        for (int k = 0; k < HD; k++)
            s = fmaf(b2[k], uw1[(ND + k) * HD + n], s);
        g_d2[n] = s;
        return;
    }
    int k = blockIdx.x;
    float s = 0.f;
    for (int m = 0; m < HD; m++)
        s = fmaf(w2[k * HD + m], uw1[(ND + m) * HD + n], s);
    float2 sp = split_f(s);
    g_Whi[OFF_W2P + k * HD + n] = sp.x;
    g_Wlo[OFF_W2P + k * HD + n] = sp.y;
}

// ---------------------------------------------------------------------------
// gemm_tc: half output (used for P and Q). 3xTF32, cp.async x2 buffered.
// ---------------------------------------------------------------------------
__global__ __launch_bounds__(256, 2) void gemm_tc(
    const float* __restrict__ A, int M, int K,
    int wOff, __half* __restrict__ Ch, int ldc, int colOff)
{
    __shared__ float As[2][64][20];
    __shared__ float Whs[2][16][136];
    __shared__ float Wls[2][16][136];

    const float* Whi = g_Whi + wOff;
    const float* Wlo = g_Wlo + wOff;

    const int tid = threadIdx.x;
    const int lane = tid & 31, warp = tid >> 5;
    const int wm = warp >> 2, wn = warp & 3;
    const int g = lane >> 2, tig = lane & 3;
    const long rBase = (long)blockIdx.x * 64;

    const int arow = tid >> 2, akq = tid & 3;
    long gArow = rBase + arow; if (gArow >= M) gArow = M - 1;
    const int wkr = tid >> 5, wcc = tid & 31;

    const int nChunks = K >> 4;

    float d[2][4][4];
    #pragma unroll
    for (int mf = 0; mf < 2; mf++)
        #pragma unroll
        for (int nf = 0; nf < 4; nf++)
            #pragma unroll
            for (int q = 0; q < 4; q++) d[mf][nf][q] = 0.f;

    cp_async16(&As[0][arow][akq * 4], A + gArow * K + akq * 4);
    cp_async16(&Whs[0][wkr][wcc * 4],     Whi + (long)wkr * 128 + wcc * 4);
    cp_async16(&Whs[0][wkr + 8][wcc * 4], Whi + (long)(wkr + 8) * 128 + wcc * 4);
    cp_async16(&Wls[0][wkr][wcc * 4],     Wlo + (long)wkr * 128 + wcc * 4);
    cp_async16(&Wls[0][wkr + 8][wcc * 4], Wlo + (long)(wkr + 8) * 128 + wcc * 4);
    CP_COMMIT();

    for (int c = 0; c < nChunks; c++) {
        if (c + 1 < nChunks) {
            int kc = (c + 1) * 16, buf = (c + 1) & 1;
            cp_async16(&As[buf][arow][akq * 4], A + gArow * K + kc + akq * 4);
            cp_async16(&Whs[buf][wkr][wcc * 4],     Whi + (long)(kc + wkr) * 128 + wcc * 4);
            cp_async16(&Whs[buf][wkr + 8][wcc * 4], Whi + (long)(kc + 8 + wkr) * 128 + wcc * 4);
            cp_async16(&Wls[buf][wkr][wcc * 4],     Wlo + (long)(kc + wkr) * 128 + wcc * 4);
            cp_async16(&Wls[buf][wkr + 8][wcc * 4], Wlo + (long)(kc + 8 + wkr) * 128 + wcc * 4);
        }
        CP_COMMIT();
        CP_WAIT1();
        __syncthreads();
        const int buf = c & 1;
        #pragma unroll
        for (int k8 = 0; k8 < 16; k8 += 8) {
            uint32_t ahi[2][4], alo[2][4], bhi[4][2], blo[4][2];
            #pragma unroll
            for (int mf = 0; mf < 2; mf++) {
                int mb = wm * 32 + mf * 16;
                float2 s0 = split_f(As[buf][mb + g][k8 + tig]);
                float2 s1 = split_f(As[buf][mb + 8 + g][k8 + tig]);
                float2 s2 = split_f(As[buf][mb + g][k8 + tig + 4]);
                float2 s3 = split_f(As[buf][mb + 8 + g][k8 + tig + 4]);
                ahi[mf][0] = __float_as_uint(s0.x); alo[mf][0] = __float_as_uint(s0.y);
                ahi[mf][1] = __float_as_uint(s1.x); alo[mf][1] = __float_as_uint(s1.y);
                ahi[mf][2] = __float_as_uint(s2.x); alo[mf][2] = __float_as_uint(s2.y);
                ahi[mf][3] = __float_as_uint(s3.x); alo[mf][3] = __float_as_uint(s3.y);
            }
            #pragma unroll
            for (int nf = 0; nf < 4; nf++) {
                int nb = wn * 32 + nf * 8;
                bhi[nf][0] = __float_as_uint(Whs[buf][k8 + tig][nb + g]);
                bhi[nf][1] = __float_as_uint(Whs[buf][k8 + tig + 4][nb + g]);
                blo[nf][0] = __float_as_uint(Wls[buf][k8 + tig][nb + g]);
                blo[nf][1] = __float_as_uint(Wls[buf][k8 + tig + 4][nb + g]);
            }
            #pragma unroll
            for (int mf = 0; mf < 2; mf++)
                #pragma unroll
                for (int nf = 0; nf < 4; nf++) {
                    mma_tf32(d[mf][nf], ahi[mf], bhi[nf]);
                    mma_tf32(d[mf][nf], alo[mf], bhi[nf]);
                    mma_tf32(d[mf][nf], ahi[mf], blo[nf]);
                }
        }
        __syncthreads();
    }

    #pragma unroll
    for (int mf = 0; mf < 2; mf++) {
        #pragma unroll
        for (int r2 = 0; r2 < 2; r2++) {
            long m = rBase + wm * 32 + mf * 16 + g + r2 * 8;
            if (m < M) {
                #pragma unroll
                for (int nf = 0; nf < 4; nf++) {
                    int n = wn * 32 + nf * 8 + 2 * tig;
                    *(__half2*)(Ch + m * ldc + colOff + n) =
                        __floats2half2_rn(d[mf][nf][r2 * 2], d[mf][nf][r2 * 2 + 1]);
                }
            }
        }
    }
}

// ---------------------------------------------------------------------------
// msg_fused: per CTA 64 undirected edges. R-gemm (K=64) -> SMEM; then
// warp-per-edge: both-direction LN + fp16 atomic scatter into g_hagg_h.
// ---------------------------------------------------------------------------
__global__ __launch_bounds__(256, 2) void msg_fused(
    const float* __restrict__ ef, const int* __restrict__ eidx,
    const float* __restrict__ b1,
    const float* __restrict__ g1, const float* __restrict__ be1)
{
    __shared__ float pool[11264];
    #define ASP(b, r, c)  pool[(b) * 1280 + (r) * 20 + (c)]
    #define WHSP(b, r, c) pool[2560 + (b) * 2176 + (r) * 136 + (c)]
    #define WLSP(b, r, c) pool[6912 + (b) * 2176 + (r) * 136 + (c)]
    #define CSP(r, c)     pool[(r) * 132 + (c)]
    __shared__ int sS[64], sT[64];

    const float* Whi = g_Whi + OFF_W1C;
    const float* Wlo = g_Wlo + OFF_W1C;

    const int tid = threadIdx.x;
    const int lane = tid & 31, warp = tid >> 5;
    const int wm = warp >> 2, wn = warp & 3;
    const int g = lane >> 2, tig = lane & 3;
    const long eBase = (long)blockIdx.x * 64;

    if (tid < 64) {
        sS[tid] = eidx[eBase + tid];
        sT[tid] = eidx[E_EDGES + eBase + tid];
    }

    const int arow = tid >> 2, akq = tid & 3;
    const long gArow = eBase + arow;
    const int wkr = tid >> 5, wcc = tid & 31;

    float d[2][4][4];
    #pragma unroll
    for (int mf = 0; mf < 2; mf++)
        #pragma unroll
        for (int nf = 0; nf < 4; nf++)
            #pragma unroll
            for (int q = 0; q < 4; q++) d[mf][nf][q] = 0.f;

    cp_async16(&ASP(0, arow, akq * 4), ef + gArow * ED + akq * 4);
    cp_async16(&WHSP(0, wkr, wcc * 4),     Whi + (long)wkr * 128 + wcc * 4);
    cp_async16(&WHSP(0, wkr + 8, wcc * 4), Whi + (long)(wkr + 8) * 128 + wcc * 4);
    cp_async16(&WLSP(0, wkr, wcc * 4),     Wlo + (long)wkr * 128 + wcc * 4);
    cp_async16(&WLSP(0, wkr + 8, wcc * 4), Wlo + (long)(wkr + 8) * 128 + wcc * 4);
    CP_COMMIT();

    for (int c = 0; c < 4; c++) {
        if (c + 1 < 4) {
            int kc = (c + 1) * 16, buf = (c + 1) & 1;
            cp_async16(&ASP(buf, arow, akq * 4), ef + gArow * ED + kc + akq * 4);
            cp_async16(&WHSP(buf, wkr, wcc * 4),     Whi + (long)(kc + wkr) * 128 + wcc * 4);
            cp_async16(&WHSP(buf, wkr + 8, wcc * 4), Whi + (long)(kc + 8 + wkr) * 128 + wcc * 4);
            cp_async16(&WLSP(buf, wkr, wcc * 4),     Wlo + (long)(kc + wkr) * 128 + wcc * 4);
            cp_async16(&WLSP(buf, wkr + 8, wcc * 4), Wlo + (long)(kc + 8 + wkr) * 128 + wcc * 4);
        }
        CP_COMMIT();
        CP_WAIT1();
        __syncthreads();
        const int buf = c & 1;
        #pragma unroll
        for (int k8 = 0; k8 < 16; k8 += 8) {
            uint32_t ahi[2][4], alo[2][4], bhi[4][2], blo[4][2];
            #pragma unroll
            for (int mf = 0; mf < 2; mf++) {
                int mb = wm * 32 + mf * 16;
                float2 s0 = split_f(ASP(buf, mb + g, k8 + tig));
                float2 s1 = split_f(ASP(buf, mb + 8 + g, k8 + tig));
                float2 s2 = split_f(ASP(buf, mb + g, k8 + tig + 4));
                float2 s3 = split_f(ASP(buf, mb + 8 + g, k8 + tig + 4));
                ahi[mf][0] = __float_as_uint(s0.x); alo[mf][0] = __float_as_uint(s0.y);
                ahi[mf][1] = __float_as_uint(s1.x); alo[mf][1] = __float_as_uint(s1.y);
                ahi[mf][2] = __float_as_uint(s2.x); alo[mf][2] = __float_as_uint(s2.y);
                ahi[mf][3] = __float_as_uint(s3.x); alo[mf][3] = __float_as_uint(s3.y);
            }
            #pragma unroll
            for (int nf2 = 0; nf2 < 4; nf2++) {
                int nb = wn * 32 + nf2 * 8;
                bhi[nf2][0] = __float_as_uint(WHSP(buf, k8 + tig, nb + g));
                bhi[nf2][1] = __float_as_uint(WHSP(buf, k8 + tig + 4, nb + g));
                blo[nf2][0] = __float_as_uint(WLSP(buf, k8 + tig, nb + g));
                blo[nf2][1] = __float_as_uint(WLSP(buf, k8 + tig + 4, nb + g));
            }
            #pragma unroll
            for (int mf = 0; mf < 2; mf++)
                #pragma unroll
                for (int nf2 = 0; nf2 < 4; nf2++) {
                    mma_tf32(d[mf][nf2], ahi[mf], bhi[nf2]);
                    mma_tf32(d[mf][nf2], alo[mf], bhi[nf2]);
                    mma_tf32(d[mf][nf2], ahi[mf], blo[nf2]);
                }
        }
        __syncthreads();
    }

    #pragma unroll
    for (int mf = 0; mf < 2; mf++)
        #pragma unroll
        for (int r2 = 0; r2 < 2; r2++) {
            int lr = wm * 32 + mf * 16 + g + r2 * 8;
            #pragma unroll
            for (int nf2 = 0; nf2 < 4; nf2++) {
                int n = wn * 32 + nf2 * 8 + 2 * tig;
                CSP(lr, n)     = d[mf][nf2][r2 * 2]     + b1[n];
                CSP(lr, n + 1) = d[mf][nf2][r2 * 2 + 1] + b1[n + 1];
            }
        }
    __syncthreads();

    float4 gg = *(const float4*)&g1[lane * 4];
    float4 bb = *(const float4*)&be1[lane * 4];
    #pragma unroll
    for (int r8 = 0; r8 < 8; r8++) {
        int lr = warp * 8 + r8;
        int s = sS[lr], t = sT[lr];
        const __half* rowS = g_PQh + (size_t)s * 256;
        const __half* rowT = g_PQh + (size_t)t * 256;
        float4 ps = ld_half4(rowS + lane * 4);
        float4 qs = ld_half4(rowS + 128 + lane * 4);
        float4 pt = ld_half4(rowT + lane * 4);
        float4 qt = ld_half4(rowT + 128 + lane * 4);
        float4 r  = *(float4*)&CSP(lr, lane * 4);

        float4 vf = make_float4(ps.x + qt.x + r.x, ps.y + qt.y + r.y,
                                ps.z + qt.z + r.z, ps.w + qt.w + r.w);
        float4 vb = make_float4(pt.x + qs.x + r.x, pt.y + qs.y + r.y,
                                pt.z + qs.z + r.z, pt.w + qs.w + r.w);

        float s1f = vf.x + vf.y + vf.z + vf.w;
        float ssf = vf.x * vf.x + vf.y * vf.y + vf.z * vf.z + vf.w * vf.w;
        float s1b = vb.x + vb.y + vb.z + vb.w;
        float ssb = vb.x * vb.x + vb.y * vb.y + vb.z * vb.z + vb.w * vb.w;
        #pragma unroll
        for (int o = 16; o >= 1; o >>= 1) {
            s1f += __shfl_xor_sync(0xffffffffu, s1f, o);
            ssf += __shfl_xor_sync(0xffffffffu, ssf, o);
            s1b += __shfl_xor_sync(0xffffffffu, s1b, o);
            ssb += __shfl_xor_sync(0xffffffffu, ssb, o);
        }
        {
            float mean = s1f * (1.0f / HD);
            float var  = ssf * (1.0f / HD) - mean * mean;
            float rstd = rsqrtf(var + LN_EPS);
            float h0 = fmaxf((vf.x - mean) * rstd * gg.x + bb.x, 0.f);
            float h1 = fmaxf((vf.y - mean) * rstd * gg.y + bb.y, 0.f);
            float h2 = fmaxf((vf.z - mean) * rstd * gg.z + bb.z, 0.f);
            float h3 = fmaxf((vf.w - mean) * rstd * gg.w + bb.w, 0.f);
            red_add_h4(g_hagg_h + (size_t)t * HD + lane * 4, h0, h1, h2, h3);
        }
        {
            float mean = s1b * (1.0f / HD);
            float var  = ssb * (1.0f / HD) - mean * mean;
            float rstd = rsqrtf(var + LN_EPS);
            float h0 = fmaxf((vb.x - mean) * rstd * gg.x + bb.x, 0.f);
            float h1 = fmaxf((vb.y - mean) * rstd * gg.y + bb.y, 0.f);
            float h2 = fmaxf((vb.z - mean) * rstd * gg.z + bb.z, 0.f);
            float h3 = fmaxf((vb.w - mean) * rstd * gg.w + bb.w, 0.f);
            red_add_h4(g_hagg_h + (size_t)s * HD + lane * 4, h0, h1, h2, h3);
        }
        if (lane == 0) { red_add_f32(g_deg + t, 1.0f); red_add_f32(g_deg + s, 1.0f); }
    }
    #undef ASP
    #undef WHSP
    #undef WLSP
    #undef CSP
}

// ---------------------------------------------------------------------------
// upd_fused2: full update path in one kernel.
//   T = nf@uw1a + hagg@W2p            (mainloop1: chunks 0-7 float nf, 8-15 half hagg)
//   H = relu(LN(T + ub1 + deg*d2))    (SMEM-staged, warp-per-row)
//   out = H@uw2 + ub2 + nf            (mainloop2: A=H in SMEM, W streamed)
// Dynamic SMEM 68608B: WH[2][16][136] @0, WL @4352, A/C region @8704 (8448):
//   ASF float A [2][64][20] @8704; ASH half A [2][64][20] @11264; CSP [64][132] @8704.
// ---------------------------------------------------------------------------
__global__ __launch_bounds__(256, 2) void upd_fused2(
    const float* __restrict__ nf, const float* __restrict__ ub1,
    const float* __restrict__ g2, const float* __restrict__ be2,
    const float* __restrict__ ub2, float* __restrict__ out)
{
    extern __shared__ float dpool[];
    #define WH2(b, r, c) dpool[(b) * 2176 + (r) * 136 + (c)]
    #define WL2(b, r, c) dpool[4352 + (b) * 2176 + (r) * 136 + (c)]
    #define ASF(b, r, c) dpool[8704 + (b) * 1280 + (r) * 20 + (c)]
    #define ASHP ((__half*)(dpool + 11264))
    #define ASH(b, r, c) ASHP[(b) * 1280 + (r) * 20 + (c)]
    #define CS2(r, c)    dpool[8704 + (r) * 132 + (c)]

    const int tid = threadIdx.x;
    const int lane = tid & 31, warp = tid >> 5;
    const int wm = warp >> 2, wn = warp & 3;
    const int g = lane >> 2, tig = lane & 3;
    const long rBase = (long)blockIdx.x * 64;

    const int arow = tid >> 2, akq = tid & 3;
    long gArow = rBase + arow; if (gArow >= N_NODES) gArow = N_NODES - 1;
    const int wkr = tid >> 5, wcc = tid & 31;

    float d[2][4][4];
    #pragma unroll
    for (int mf = 0; mf < 2; mf++)
        #pragma unroll
        for (int nf2 = 0; nf2 < 4; nf2++)
            #pragma unroll
            for (int q = 0; q < 4; q++) d[mf][nf2][q] = 0.f;

    // ---- mainloop1 prologue (chunk 0: float nf, W=uw1a) ----
    {
        const float* Wh0 = g_Whi + OFF_UW1;
        const float* Wl0 = g_Wlo + OFF_UW1;
        cp_async16(&ASF(0, arow, akq * 4), nf + gArow * HD + akq * 4);
        cp_async16(&WH2(0, wkr, wcc * 4),     Wh0 + (long)wkr * 128 + wcc * 4);
        cp_async16(&WH2(0, wkr + 8, wcc * 4), Wh0 + (long)(wkr + 8) * 128 + wcc * 4);
        cp_async16(&WL2(0, wkr, wcc * 4),     Wl0 + (long)wkr * 128 + wcc * 4);
        cp_async16(&WL2(0, wkr + 8, wcc * 4), Wl0 + (long)(wkr + 8) * 128 + wcc * 4);
        CP_COMMIT();
    }

    for (int c = 0; c < 16; c++) {
        if (c + 1 < 16) {
            int cn = c + 1, buf = cn & 1;
            int kc = (cn & 7) * 16;
            const float* Whn = g_Whi + ((cn < 8) ? OFF_UW1 : OFF_W2P);
            const float* Wln = g_Wlo + ((cn < 8) ? OFF_UW1 : OFF_W2P);
            if (cn < 8)
                cp_async16(&ASF(buf, arow, akq * 4), nf + gArow * HD + kc + akq * 4);
            else
                cp_async8(&ASH(buf, arow, akq * 4), g_hagg_h + gArow * HD + kc + akq * 4);
            cp_async16(&WH2(buf, wkr, wcc * 4),     Whn + (long)(kc + wkr) * 128 + wcc * 4);
            cp_async16(&WH2(buf, wkr + 8, wcc * 4), Whn + (long)(kc + 8 + wkr) * 128 + wcc * 4);
            cp_async16(&WL2(buf, wkr, wcc * 4),     Wln + (long)(kc + wkr) * 128 + wcc * 4);
            cp_async16(&WL2(buf, wkr + 8, wcc * 4), Wln + (long)(kc + 8 + wkr) * 128 + wcc * 4);
        }
        CP_COMMIT();
        CP_WAIT1();
        __syncthreads();
        const int buf = c & 1;
        #pragma unroll
        for (int k8 = 0; k8 < 16; k8 += 8) {
            uint32_t ahi[2][4], alo[2][4], bhi[4][2], blo[4][2];
            #pragma unroll
            for (int mf = 0; mf < 2; mf++) {
                int mb = wm * 32 + mf * 16;
                float a0, a1, a2, a3;
                if (c < 8) {
                    a0 = ASF(buf, mb + g, k8 + tig);
                    a1 = ASF(buf, mb + 8 + g, k8 + tig);
                    a2 = ASF(buf, mb + g, k8 + tig + 4);
                    a3 = ASF(buf, mb + 8 + g, k8 + tig + 4);
                } else {
                    a0 = __half2float(ASH(buf, mb + g, k8 + tig));
                    a1 = __half2float(ASH(buf, mb + 8 + g, k8 + tig));
                    a2 = __half2float(ASH(buf, mb + g, k8 + tig + 4));
                    a3 = __half2float(ASH(buf, mb + 8 + g, k8 + tig + 4));
                }
                float2 s0 = split_f(a0), s1 = split_f(a1);
                float2 s2 = split_f(a2), s3 = split_f(a3);
                ahi[mf][0] = __float_as_uint(s0.x); alo[mf][0] = __float_as_uint(s0.y);
                ahi[mf][1] = __float_as_uint(s1.x); alo[mf][1] = __float_as_uint(s1.y);
                ahi[mf][2] = __float_as_uint(s2.x); alo[mf][2] = __float_as_uint(s2.y);
                ahi[mf][3] = __float_as_uint(s3.x); alo[mf][3] = __float_as_uint(s3.y);
            }
            #pragma unroll
            for (int nf2 = 0; nf2 < 4; nf2++) {
                int nb = wn * 32 + nf2 * 8;
                bhi[nf2][0] = __float_as_uint(WH2(buf, k8 + tig, nb + g));
                bhi[nf2][1] = __float_as_uint(WH2(buf, k8 + tig + 4, nb + g));
                blo[nf2][0] = __float_as_uint(WL2(buf, k8 + tig, nb + g));
                blo[nf2][1] = __float_as_uint(WL2(buf, k8 + tig + 4, nb + g));
            }
            #pragma unroll
            for (int mf = 0; mf < 2; mf++)
                #pragma unroll
                for (int nf2 = 0; nf2 < 4; nf2++) {
                    mma_tf32(d[mf][nf2], ahi[mf], bhi[nf2]);
                    mma_tf32(d[mf][nf2], alo[mf], bhi[nf2]);
                    mma_tf32(d[mf][nf2], ahi[mf], blo[nf2]);
                }
        }
        __syncthreads();
    }

    // ---- stage T tile into CSP ----
    #pragma unroll
    for (int mf = 0; mf < 2; mf++)
        #pragma unroll
        for (int r2 = 0; r2 < 2; r2++) {
            int lr = wm * 32 + mf * 16 + g + r2 * 8;
            #pragma unroll
            for (int nf2 = 0; nf2 < 4; nf2++) {
                int n = wn * 32 + nf2 * 8 + 2 * tig;
                CS2(lr, n)     = d[mf][nf2][r2 * 2];
                CS2(lr, n + 1) = d[mf][nf2][r2 * 2 + 1];
            }
        }
    __syncthreads();

    // ---- LN (+ub1 + deg*d2) -> relu -> H written back into CSP ----
    #pragma unroll
    for (int r8 = 0; r8 < 8; r8++) {
        int lr = warp * 8 + r8;
        long row = rBase + lr;
        long rowc = row < N_NODES ? row : N_NODES - 1;
        float dg = g_deg[rowc];
        int cc = lane * 4;
        float4 v = *(float4*)&CS2(lr, cc);
        float4 ub = *(const float4*)&ub1[cc];
        float4 dd = *(const float4*)&g_d2[cc];
        v.x += ub.x + dg * dd.x; v.y += ub.y + dg * dd.y;
        v.z += ub.z + dg * dd.z; v.w += ub.w + dg * dd.w;
        float s1 = v.x + v.y + v.z + v.w;
        float ss = v.x * v.x + v.y * v.y + v.z * v.z + v.w * v.w;
        #pragma unroll
        for (int o = 16; o >= 1; o >>= 1) {
            s1 += __shfl_xor_sync(0xffffffffu, s1, o);
            ss += __shfl_xor_sync(0xffffffffu, ss, o);
        }
        float mean = s1 * (1.0f / HD);
        float var  = ss * (1.0f / HD) - mean * mean;
        float rstd = rsqrtf(var + LN_EPS);
        float4 gg = *(const float4*)&g2[cc];
        float4 bb = *(const float4*)&be2[cc];
        float4 h;
        h.x = fmaxf((v.x - mean) * rstd * gg.x + bb.x, 0.f);
        h.y = fmaxf((v.y - mean) * rstd * gg.y + bb.y, 0.f);
        h.z = fmaxf((v.z - mean) * rstd * gg.z + bb.z, 0.f);
        h.w = fmaxf((v.w - mean) * rstd * gg.w + bb.w, 0.f);
        *(float4*)&CS2(lr, cc) = h;
    }
    __syncthreads();

    // ---- mainloop2: out-tile = H(CSP) @ uw2; W streamed double-buffered ----
    #pragma unroll
    for (int mf = 0; mf < 2; mf++)
        #pragma unroll
        for (int nf2 = 0; nf2 < 4; nf2++)
            #pragma unroll
            for (int q = 0; q < 4; q++) d[mf][nf2][q] = 0.f;
    {
        const float* Wh0 = g_Whi + OFF_UW2;
        const float* Wl0 = g_Wlo + OFF_UW2;
        cp_async16(&WH2(0, wkr, wcc * 4),     Wh0 + (long)wkr * 128 + wcc * 4);
        cp_async16(&WH2(0, wkr + 8, wcc * 4), Wh0 + (long)(wkr + 8) * 128 + wcc * 4);
        cp_async16(&WL2(0, wkr, wcc * 4),     Wl0 + (long)wkr * 128 + wcc * 4);
        cp_async16(&WL2(0, wkr + 8, wcc * 4), Wl0 + (long)(wkr + 8) * 128 + wcc * 4);
        CP_COMMIT();
    }
    for (int c = 0; c < 8; c++) {
        if (c + 1 < 8) {
            int kc = (c + 1) * 16, buf = (c + 1) & 1;
            const float* Whn = g_Whi + OFF_UW2;
            const float* Wln = g_Wlo + OFF_UW2;
            cp_async16(&WH2(buf, wkr, wcc * 4),     Whn + (long)(kc + wkr) * 128 + wcc * 4);
            cp_async16(&WH2(buf, wkr + 8, wcc * 4), Whn + (long)(kc + 8 + wkr) * 128 + wcc * 4);
            cp_async16(&WL2(buf, wkr, wcc * 4),     Wln + (long)(kc + wkr) * 128 + wcc * 4);
            cp_async16(&WL2(buf, wkr + 8, wcc * 4), Wln + (long)(kc + 8 + wkr) * 128 + wcc * 4);
        }
        CP_COMMIT();
        CP_WAIT1();
        __syncthreads();
        const int buf = c & 1;
        const int kc0 = c * 16;
        #pragma unroll
        for (int k8 = 0; k8 < 16; k8 += 8) {
            uint32_t ahi[2][4], alo[2][4], bhi[4][2], blo[4][2];
            #pragma unroll
            for (int mf = 0; mf < 2; mf++) {
                int mb = wm * 32 + mf * 16;
                float2 s0 = split_f(CS2(mb + g,     kc0 + k8 + tig));
                float2 s1 = split_f(CS2(mb + 8 + g, kc0 + k8 + tig));
                float2 s2 = split_f(CS2(mb + g,     kc0 + k8 + tig + 4));
                float2 s3 = split_f(CS2(mb + 8 + g, kc0 + k8 + tig + 4));
                ahi[mf][0] = __float_as_uint(s0.x); alo[mf][0] = __float_as_uint(s0.y);
                ahi[mf][1] = __float_as_uint(s1.x); alo[mf][1] = __float_as_uint(s1.y);
                ahi[mf][2] = __float_as_uint(s2.x); alo[mf][2] = __float_as_uint(s2.y);
                ahi[mf][3] = __float_as_uint(s3.x); alo[mf][3] = __float_as_uint(s3.y);
            }
            #pragma unroll
            for (int nf2 = 0; nf2 < 4; nf2++) {
                int nb = wn * 32 + nf2 * 8;
                bhi[nf2][0] = __float_as_uint(WH2(buf, k8 + tig, nb + g));
                bhi[nf2][1] = __float_as_uint(WH2(buf, k8 + tig + 4, nb + g));
                blo[nf2][0] = __float_as_uint(WL2(buf, k8 + tig, nb + g));
                blo[nf2][1] = __float_as_uint(WL2(buf, k8 + tig + 4, nb + g));
            }
            #pragma unroll
            for (int mf = 0; mf < 2; mf++)
                #pragma unroll
                for (int nf2 = 0; nf2 < 4; nf2++) {
                    mma_tf32(d[mf][nf2], ahi[mf], bhi[nf2]);
                    mma_tf32(d[mf][nf2], alo[mf], bhi[nf2]);
                    mma_tf32(d[mf][nf2], ahi[mf], blo[nf2]);
                }
        }
        __syncthreads();
    }

    // ---- epilogue: out = d + ub2 + nf ----
    #pragma unroll
    for (int mf = 0; mf < 2; mf++) {
        #pragma unroll
        for (int r2 = 0; r2 < 2; r2++) {
            long m = rBase + wm * 32 + mf * 16 + g + r2 * 8;
            if (m < N_NODES) {
                #pragma unroll
                for (int nf2 = 0; nf2 < 4; nf2++) {
                    int n = wn * 32 + nf2 * 8 + 2 * tig;
                    float2 rr = *(const float2*)(nf + m * 128 + n);
                    float v0 = d[mf][nf2][r2 * 2]     + ub2[n]     + rr.x;
                    float v1 = d[mf][nf2][r2 * 2 + 1] + ub2[n + 1] + rr.y;
                    *(float2*)(out + m * 128 + n) = make_float2(v0, v1);
                }
            }
        }
    }
}

extern "C" void kernel_launch(void* const* d_in, const int* in_sizes, int n_in,
                              void* d_out, int out_size)
{
    const float* nf   = (const float*)d_in[0];
    const float* ef   = (const float*)d_in[1];
    const int*   eidx = (const int*)  d_in[2];
    const float* w1   = (const float*)d_in[3];
    const float* b1   = (const float*)d_in[4];
    const float* g1   = (const float*)d_in[5];
    const float* be1  = (const float*)d_in[6];
    const float* w2   = (const float*)d_in[7];
    const float* b2   = (const float*)d_in[8];
    const float* uw1  = (const float*)d_in[9];
    const float* ub1  = (const float*)d_in[10];
    const float* g2   = (const float*)d_in[11];
    const float* be2  = (const float*)d_in[12];
    const float* uw2  = (const float*)d_in[13];
    const float* ub2  = (const float*)d_in[14];
    float* out = (float*)d_out;

    __half* dPQ;
    cudaGetSymbolAddress((void**)&dPQ, g_PQh);

    const int gN = (N_NODES + 63) / 64;   // 1563
    const int gE = E_EDGES / 64;          // 6250

    const int UPD_SMEM = 17152 * 4;       // 68608 B
    cudaFuncSetAttribute(upd_fused2, cudaFuncAttributeMaxDynamicSharedMemorySize, UPD_SMEM);

    zero_kernel<<<592, 256>>>();
    split_all_kernel<<<(N_SPLIT_IN + 255) / 256, 256>>>(w1, uw1, uw2);
    w2p_kernel<<<129, 128>>>(w2, uw1, b2);
    // P (cols 0:128 of PQ), Q (cols 128:256)
    gemm_tc<<<gN, 256>>>(nf, N_NODES, ND, OFF_W1, dPQ, 256, 0);
    gemm_tc<<<gN, 256>>>(nf, N_NODES, ND, OFF_W1 + ND * HD, dPQ, 256, 128);
    // fused message: R-gemm + gather + LN + fp16 scatter
    msg_fused<<<gE, 256>>>(ef, eidx, b1, g1, be1);
    // fused update: GEMM1 + LN + GEMM2 + residual -> out
    upd_fused2<<<gN, 256, UPD_SMEM>>>(nf, ub1, g2, be2, ub2, out);
}

// round 13
// speedup vs baseline: 1.8923x; 1.3060x over previous
#include <cuda_runtime.h>
#include <cuda_fp16.h>
#include <math.h>
#include <stdint.h>

#define N_NODES 100000
#define E_EDGES 400000
#define ND 128
#define ED 64
#define HD 128
#define LN_EPS 1e-5f

// Scratch (__device__ globals: allocation-free rule)
__device__ __half g_hagg_h[(size_t)N_NODES * HD];  // fp16 atomic accumulator
__device__ float  g_deg[N_NODES];
__device__ __half g_PQh[(size_t)N_NODES * 256];    // [node][0:128]=P, [128:256]=Q
__device__ float  g_d2[HD];

// Pre-split weight planes (hi/lo TF32). Flat layout:
//   w1  @ 0       (320*128 = 40960)  [W1c rows at 32768]
//   uw1 @ 40960   (256*128 = 32768)
//   uw2 @ 73728   (128*128 = 16384)
//   W2p @ 90112   (128*128 = 16384)
#define OFF_W1   0
#define OFF_W1C  32768
#define OFF_UW1  40960
#define OFF_UW2  73728
#define OFF_W2P  90112
#define N_SPLIT_IN 90112
__device__ float g_Whi[106496];
__device__ float g_Wlo[106496];

// ---------------- helpers ----------------
__device__ __forceinline__ void red_add_f32(float* p, float v) {
    asm volatile("red.global.add.f32 [%0], %1;" :: "l"(p), "f"(v) : "memory");
}
__device__ __forceinline__ void red_add_h4(__half* p, float a, float b, float c, float d) {
    __half2 v01 = __floats2half2_rn(a, b);
    __half2 v23 = __floats2half2_rn(c, d);
    uint32_t u01 = *reinterpret_cast<uint32_t*>(&v01);
    uint32_t u23 = *reinterpret_cast<uint32_t*>(&v23);
    asm volatile("red.global.add.noftz.f16x2 [%0], %1;" :: "l"(p),     "r"(u01) : "memory");
    asm volatile("red.global.add.noftz.f16x2 [%0], %1;" :: "l"(p + 2), "r"(u23) : "memory");
}
__device__ __forceinline__ float2 split_f(float x) {
    uint32_t hi;
    asm("cvt.rna.tf32.f32 %0, %1;" : "=r"(hi) : "f"(x));
    float h = __uint_as_float(hi);
    float r = x - h;
    uint32_t lo;
    asm("cvt.rna.tf32.f32 %0, %1;" : "=r"(lo) : "f"(r));
    return make_float2(h, __uint_as_float(lo));
}
__device__ __forceinline__ uint32_t tf32_hi(float x) {
    uint32_t h;
    asm("cvt.rna.tf32.f32 %0, %1;" : "=r"(h) : "f"(x));
    return h;
}
__device__ __forceinline__ void mma_tf32(float d[4], const uint32_t a[4], const uint32_t b[2]) {
    asm("mma.sync.aligned.m16n8k8.row.col.f32.tf32.tf32.f32 "
        "{%0,%1,%2,%3}, {%4,%5,%6,%7}, {%8,%9}, {%0,%1,%2,%3};"
        : "+f"(d[0]), "+f"(d[1]), "+f"(d[2]), "+f"(d[3])
        : "r"(a[0]), "r"(a[1]), "r"(a[2]), "r"(a[3]), "r"(b[0]), "r"(b[1]));
}
__device__ __forceinline__ void cp_async16(void* smem, const void* gmem) {
    uint32_t s = (uint32_t)__cvta_generic_to_shared(smem);
    asm volatile("cp.async.cg.shared.global [%0], [%1], 16;" :: "r"(s), "l"(gmem));
}
__device__ __forceinline__ void cp_async8(void* smem, const void* gmem) {
    uint32_t s = (uint32_t)__cvta_generic_to_shared(smem);
    asm volatile("cp.async.ca.shared.global [%0], [%1], 8;" :: "r"(s), "l"(gmem));
}
#define CP_COMMIT() asm volatile("cp.async.commit_group;")
#define CP_WAIT1()  asm volatile("cp.async.wait_group 1;")

__device__ __forceinline__ float4 ld_half4(const __half* p) {
    uint2 u = *(const uint2*)p;
    __half2 a = *reinterpret_cast<__half2*>(&u.x);
    __half2 b = *reinterpret_cast<__half2*>(&u.y);
    float2 fa = __half22float2(a), fb = __half22float2(b);
    return make_float4(fa.x, fa.y, fb.x, fb.y);
}

__global__ void zero_kernel() {
    uint4* p = reinterpret_cast<uint4*>(g_hagg_h);
    const int n16 = (int)(((size_t)N_NODES * HD * 2) / 16);
    uint4 z = make_uint4(0, 0, 0, 0);
    for (int i = blockIdx.x * blockDim.x + threadIdx.x; i < n16;
         i += gridDim.x * blockDim.x)
        p[i] = z;
    for (int i = blockIdx.x * blockDim.x + threadIdx.x; i < N_NODES;
         i += gridDim.x * blockDim.x)
        g_deg[i] = 0.f;
}

__global__ void split_all_kernel(const float* __restrict__ w1,
                                 const float* __restrict__ uw1,
                                 const float* __restrict__ uw2)
{
    int i = blockIdx.x * blockDim.x + threadIdx.x;
    if (i >= N_SPLIT_IN) return;
    float v;
    if (i < OFF_UW1)       v = w1[i];
    else if (i < OFF_UW2)  v = uw1[i - OFF_UW1];
    else                   v = uw2[i - OFF_UW2];
    float2 s = split_f(v);
    g_Whi[i] = s.x;
    g_Wlo[i] = s.y;
}

// W2p = W2 @ uw1b (+split); block 128 computes d2 = b2 @ uw1b.
__global__ void w2p_kernel(const float* __restrict__ w2,
                           const float* __restrict__ uw1,
                           const float* __restrict__ b2) {
    int n = threadIdx.x;
    if (blockIdx.x == 128) {
        float s = 0.f;
        for (int k = 0; k < HD; k++)
            s = fmaf(b2[k], uw1[(ND + k) * HD + n], s);
        g_d2[n] = s;
        return;
    }
    int k = blockIdx.x;
    float s = 0.f;
    for (int m = 0; m < HD; m++)
        s = fmaf(w2[k * HD + m], uw1[(ND + m) * HD + n], s);
    float2 sp = split_f(s);
    g_Whi[OFF_W2P + k * HD + n] = sp.x;
    g_Wlo[OFF_W2P + k * HD + n] = sp.y;
}

// ---------------------------------------------------------------------------
// gemm_pq: P and Q in ONE pass. Full 64x128 nf tile cached in SMEM (stride
// 132 = conflict-free), two W-panel mainloops (W1a then W1b) with hi-plane
// double-buffered streaming. Single-term TF32 (fp16-grade output).
// Dynamic SMEM: A[64][132] @0 (8448 f) + WH[2][16][136] @8448 (4352 f)
//             = 12800 floats = 51200 B.
// ---------------------------------------------------------------------------
__global__ __launch_bounds__(256, 2) void gemm_pq(
    const float* __restrict__ nf, __half* __restrict__ PQ)
{
    extern __shared__ float sp[];
    #define AT(r, c)     sp[(r) * 132 + (c)]
    #define WPH(b, r, c) sp[8448 + (b) * 2176 + (r) * 136 + (c)]

    const int tid = threadIdx.x;
    const int lane = tid & 31, warp = tid >> 5;
    const int wm = warp >> 2, wn = warp & 3;
    const int g = lane >> 2, tig = lane & 3;
    const long rBase = (long)blockIdx.x * 64;

    const int arow = tid >> 2, akq = tid & 3;
    long gArow = rBase + arow; if (gArow >= N_NODES) gArow = N_NODES - 1;
    const int wkr = tid >> 5, wcc = tid & 31;

    // prologue: full A tile (8 chunks) + W(panel0, chunk0)
    #pragma unroll
    for (int j = 0; j < 8; j++)
        cp_async16(&AT(arow, j * 16 + akq * 4), nf + gArow * ND + j * 16 + akq * 4);
    {
        const float* Wh = g_Whi + OFF_W1;
        cp_async16(&WPH(0, wkr, wcc * 4),     Wh + (long)wkr * 128 + wcc * 4);
        cp_async16(&WPH(0, wkr + 8, wcc * 4), Wh + (long)(wkr + 8) * 128 + wcc * 4);
    }
    CP_COMMIT();

    float d[2][4][4];
    #pragma unroll
    for (int mf = 0; mf < 2; mf++)
        #pragma unroll
        for (int nf2 = 0; nf2 < 4; nf2++)
            #pragma unroll
            for (int q = 0; q < 4; q++) d[mf][nf2][q] = 0.f;

    for (int cg = 0; cg < 16; cg++) {           // panel = cg>>3, chunk = cg&7
        if (cg + 1 < 16) {
            int buf = (cg + 1) & 1;
            int kc = ((cg + 1) & 7) * 16;
            const float* Wh = g_Whi + OFF_W1 + ((cg + 1) >> 3) * (ND * HD);
            cp_async16(&WPH(buf, wkr, wcc * 4),     Wh + (long)(kc + wkr) * 128 + wcc * 4);
            cp_async16(&WPH(buf, wkr + 8, wcc * 4), Wh + (long)(kc + 8 + wkr) * 128 + wcc * 4);
        }
        CP_COMMIT();
        CP_WAIT1();
        __syncthreads();
        const int buf = cg & 1;
        const int kc0 = (cg & 7) * 16;
        #pragma unroll
        for (int k8 = 0; k8 < 16; k8 += 8) {
            uint32_t ahi[2][4], bhi[4][2];
            #pragma unroll
            for (int mf = 0; mf < 2; mf++) {
                int mb = wm * 32 + mf * 16;
                ahi[mf][0] = tf32_hi(AT(mb + g,     kc0 + k8 + tig));
                ahi[mf][1] = tf32_hi(AT(mb + 8 + g, kc0 + k8 + tig));
                ahi[mf][2] = tf32_hi(AT(mb + g,     kc0 + k8 + tig + 4));
                ahi[mf][3] = tf32_hi(AT(mb + 8 + g, kc0 + k8 + tig + 4));
            }
            #pragma unroll
            for (int nf2 = 0; nf2 < 4; nf2++) {
                int nb = wn * 32 + nf2 * 8;
                bhi[nf2][0] = tf32_hi(WPH(buf, k8 + tig,     nb + g));
                bhi[nf2][1] = tf32_hi(WPH(buf, k8 + tig + 4, nb + g));
            }
            #pragma unroll
            for (int mf = 0; mf < 2; mf++)
                #pragma unroll
                for (int nf2 = 0; nf2 < 4; nf2++)
                    mma_tf32(d[mf][nf2], ahi[mf], bhi[nf2]);
        }
        __syncthreads();

        if ((cg & 7) == 7) {
            // end of panel: write P (colOff 0) or Q (colOff 128), reset accum
            int colOff = (cg >> 3) * 128;
            #pragma unroll
            for (int mf = 0; mf < 2; mf++)
                #pragma unroll
                for (int r2 = 0; r2 < 2; r2++) {
                    long m = rBase + wm * 32 + mf * 16 + g + r2 * 8;
                    if (m < N_NODES) {
                        #pragma unroll
                        for (int nf2 = 0; nf2 < 4; nf2++) {
                            int n = wn * 32 + nf2 * 8 + 2 * tig;
                            *(__half2*)(PQ + m * 256 + colOff + n) =
                                __floats2half2_rn(d[mf][nf2][r2 * 2], d[mf][nf2][r2 * 2 + 1]);
                        }
                    }
                }
            #pragma unroll
            for (int mf = 0; mf < 2; mf++)
                #pragma unroll
                for (int nf2 = 0; nf2 < 4; nf2++)
                    #pragma unroll
                    for (int q = 0; q < 4; q++) d[mf][nf2][q] = 0.f;
        }
    }
    #undef AT
    #undef WPH
}

// ---------------------------------------------------------------------------
// msg_fused: per CTA 64 undirected edges. Single-term TF32 R-gemm (K=64)
// -> SMEM; then warp-per-edge both-direction LN + fp16 atomic scatter.
// ---------------------------------------------------------------------------
__global__ __launch_bounds__(256, 2) void msg_fused(
    const float* __restrict__ ef, const int* __restrict__ eidx,
    const float* __restrict__ b1,
    const float* __restrict__ g1, const float* __restrict__ be1)
{
    __shared__ float pool[8448];
    #define ASP(b, r, c)  pool[(b) * 1280 + (r) * 20 + (c)]
    #define WHSP(b, r, c) pool[2560 + (b) * 2176 + (r) * 136 + (c)]
    #define CSP(r, c)     pool[(r) * 132 + (c)]
    __shared__ int sS[64], sT[64];

    const float* Whi = g_Whi + OFF_W1C;

    const int tid = threadIdx.x;
    const int lane = tid & 31, warp = tid >> 5;
    const int wm = warp >> 2, wn = warp & 3;
    const int g = lane >> 2, tig = lane & 3;
    const long eBase = (long)blockIdx.x * 64;

    if (tid < 64) {
        sS[tid] = eidx[eBase + tid];
        sT[tid] = eidx[E_EDGES + eBase + tid];
    }

    const int arow = tid >> 2, akq = tid & 3;
    const long gArow = eBase + arow;
    const int wkr = tid >> 5, wcc = tid & 31;

    float d[2][4][4];
    #pragma unroll
    for (int mf = 0; mf < 2; mf++)
        #pragma unroll
        for (int nf2 = 0; nf2 < 4; nf2++)
            #pragma unroll
            for (int q = 0; q < 4; q++) d[mf][nf2][q] = 0.f;

    cp_async16(&ASP(0, arow, akq * 4), ef + gArow * ED + akq * 4);
    cp_async16(&WHSP(0, wkr, wcc * 4),     Whi + (long)wkr * 128 + wcc * 4);
    cp_async16(&WHSP(0, wkr + 8, wcc * 4), Whi + (long)(wkr + 8) * 128 + wcc * 4);
    CP_COMMIT();

    for (int c = 0; c < 4; c++) {
        if (c + 1 < 4) {
            int kc = (c + 1) * 16, buf = (c + 1) & 1;
            cp_async16(&ASP(buf, arow, akq * 4), ef + gArow * ED + kc + akq * 4);
            cp_async16(&WHSP(buf, wkr, wcc * 4),     Whi + (long)(kc + wkr) * 128 + wcc * 4);
            cp_async16(&WHSP(buf, wkr + 8, wcc * 4), Whi + (long)(kc + 8 + wkr) * 128 + wcc * 4);
        }
        CP_COMMIT();
        CP_WAIT1();
        __syncthreads();
        const int buf = c & 1;
        #pragma unroll
        for (int k8 = 0; k8 < 16; k8 += 8) {
            uint32_t ahi[2][4], bhi[4][2];
            #pragma unroll
            for (int mf = 0; mf < 2; mf++) {
                int mb = wm * 32 + mf * 16;
                ahi[mf][0] = tf32_hi(ASP(buf, mb + g,     k8 + tig));
                ahi[mf][1] = tf32_hi(ASP(buf, mb + 8 + g, k8 + tig));
                ahi[mf][2] = tf32_hi(ASP(buf, mb + g,     k8 + tig + 4));
                ahi[mf][3] = tf32_hi(ASP(buf, mb + 8 + g, k8 + tig + 4));
            }
            #pragma unroll
            for (int nf2 = 0; nf2 < 4; nf2++) {
                int nb = wn * 32 + nf2 * 8;
                bhi[nf2][0] = tf32_hi(WHSP(buf, k8 + tig,     nb + g));
                bhi[nf2][1] = tf32_hi(WHSP(buf, k8 + tig + 4, nb + g));
            }
            #pragma unroll
            for (int mf = 0; mf < 2; mf++)
                #pragma unroll
                for (int nf2 = 0; nf2 < 4; nf2++)
                    mma_tf32(d[mf][nf2], ahi[mf], bhi[nf2]);
        }
        __syncthreads();
    }

    #pragma unroll
    for (int mf = 0; mf < 2; mf++)
        #pragma unroll
        for (int r2 = 0; r2 < 2; r2++) {
            int lr = wm * 32 + mf * 16 + g + r2 * 8;
            #pragma unroll
            for (int nf2 = 0; nf2 < 4; nf2++) {
                int n = wn * 32 + nf2 * 8 + 2 * tig;
                CSP(lr, n)     = d[mf][nf2][r2 * 2]     + b1[n];
                CSP(lr, n + 1) = d[mf][nf2][r2 * 2 + 1] + b1[n + 1];
            }
        }
    __syncthreads();

    float4 gg = *(const float4*)&g1[lane * 4];
    float4 bb = *(const float4*)&be1[lane * 4];
    #pragma unroll
    for (int r8 = 0; r8 < 8; r8++) {
        int lr = warp * 8 + r8;
        int s = sS[lr], t = sT[lr];
        const __half* rowS = g_PQh + (size_t)s * 256;
        const __half* rowT = g_PQh + (size_t)t * 256;
        float4 ps = ld_half4(rowS + lane * 4);
        float4 qs = ld_half4(rowS + 128 + lane * 4);
        float4 pt = ld_half4(rowT + lane * 4);
        float4 qt = ld_half4(rowT + 128 + lane * 4);
        float4 r  = *(float4*)&CSP(lr, lane * 4);

        float4 vf = make_float4(ps.x + qt.x + r.x, ps.y + qt.y + r.y,
                                ps.z + qt.z + r.z, ps.w + qt.w + r.w);
        float4 vb = make_float4(pt.x + qs.x + r.x, pt.y + qs.y + r.y,
                                pt.z + qs.z + r.z, pt.w + qs.w + r.w);

        float s1f = vf.x + vf.y + vf.z + vf.w;
        float ssf = vf.x * vf.x + vf.y * vf.y + vf.z * vf.z + vf.w * vf.w;
        float s1b = vb.x + vb.y + vb.z + vb.w;
        float ssb = vb.x * vb.x + vb.y * vb.y + vb.z * vb.z + vb.w * vb.w;
        #pragma unroll
        for (int o = 16; o >= 1; o >>= 1) {
            s1f += __shfl_xor_sync(0xffffffffu, s1f, o);
            ssf += __shfl_xor_sync(0xffffffffu, ssf, o);
            s1b += __shfl_xor_sync(0xffffffffu, s1b, o);
            ssb += __shfl_xor_sync(0xffffffffu, ssb, o);
        }
        {
            float mean = s1f * (1.0f / HD);
            float var  = ssf * (1.0f / HD) - mean * mean;
            float rstd = rsqrtf(var + LN_EPS);
            float h0 = fmaxf((vf.x - mean) * rstd * gg.x + bb.x, 0.f);
            float h1 = fmaxf((vf.y - mean) * rstd * gg.y + bb.y, 0.f);
            float h2 = fmaxf((vf.z - mean) * rstd * gg.z + bb.z, 0.f);
            float h3 = fmaxf((vf.w - mean) * rstd * gg.w + bb.w, 0.f);
            red_add_h4(g_hagg_h + (size_t)t * HD + lane * 4, h0, h1, h2, h3);
        }
        {
            float mean = s1b * (1.0f / HD);
            float var  = ssb * (1.0f / HD) - mean * mean;
            float rstd = rsqrtf(var + LN_EPS);
            float h0 = fmaxf((vb.x - mean) * rstd * gg.x + bb.x, 0.f);
            float h1 = fmaxf((vb.y - mean) * rstd * gg.y + bb.y, 0.f);
            float h2 = fmaxf((vb.z - mean) * rstd * gg.z + bb.z, 0.f);
            float h3 = fmaxf((vb.w - mean) * rstd * gg.w + bb.w, 0.f);
            red_add_h4(g_hagg_h + (size_t)s * HD + lane * 4, h0, h1, h2, h3);
        }
        if (lane == 0) { red_add_f32(g_deg + t, 1.0f); red_add_f32(g_deg + s, 1.0f); }
    }
    #undef ASP
    #undef WHSP
    #undef CSP
}

// ---------------------------------------------------------------------------
// upd_fused2: full update path in one kernel (3-term TF32, unchanged R12).
// ---------------------------------------------------------------------------
__global__ __launch_bounds__(256, 2) void upd_fused2(
    const float* __restrict__ nf, const float* __restrict__ ub1,
    const float* __restrict__ g2, const float* __restrict__ be2,
    const float* __restrict__ ub2, float* __restrict__ out)
{
    extern __shared__ float dpool[];
    #define WH2(b, r, c) dpool[(b) * 2176 + (r) * 136 + (c)]
    #define WL2(b, r, c) dpool[4352 + (b) * 2176 + (r) * 136 + (c)]
    #define ASF(b, r, c) dpool[8704 + (b) * 1280 + (r) * 20 + (c)]
    #define ASHP ((__half*)(dpool + 11264))
    #define ASH(b, r, c) ASHP[(b) * 1280 + (r) * 20 + (c)]
    #define CS2(r, c)    dpool[8704 + (r) * 132 + (c)]

    const int tid = threadIdx.x;
    const int lane = tid & 31, warp = tid >> 5;
    const int wm = warp >> 2, wn = warp & 3;
    const int g = lane >> 2, tig = lane & 3;
    const long rBase = (long)blockIdx.x * 64;

    const int arow = tid >> 2, akq = tid & 3;
    long gArow = rBase + arow; if (gArow >= N_NODES) gArow = N_NODES - 1;
    const int wkr = tid >> 5, wcc = tid & 31;

    float d[2][4][4];
    #pragma unroll
    for (int mf = 0; mf < 2; mf++)
        #pragma unroll
        for (int nf2 = 0; nf2 < 4; nf2++)
            #pragma unroll
            for (int q = 0; q < 4; q++) d[mf][nf2][q] = 0.f;

    {
        const float* Wh0 = g_Whi + OFF_UW1;
        const float* Wl0 = g_Wlo + OFF_UW1;
        cp_async16(&ASF(0, arow, akq * 4), nf + gArow * HD + akq * 4);
        cp_async16(&WH2(0, wkr, wcc * 4),     Wh0 + (long)wkr * 128 + wcc * 4);
        cp_async16(&WH2(0, wkr + 8, wcc * 4), Wh0 + (long)(wkr + 8) * 128 + wcc * 4);
        cp_async16(&WL2(0, wkr, wcc * 4),     Wl0 + (long)wkr * 128 + wcc * 4);
        cp_async16(&WL2(0, wkr + 8, wcc * 4), Wl0 + (long)(wkr + 8) * 128 + wcc * 4);
        CP_COMMIT();
    }

    for (int c = 0; c < 16; c++) {
        if (c + 1 < 16) {
            int cn = c + 1, buf = cn & 1;
            int kc = (cn & 7) * 16;
            const float* Whn = g_Whi + ((cn < 8) ? OFF_UW1 : OFF_W2P);
            const float* Wln = g_Wlo + ((cn < 8) ? OFF_UW1 : OFF_W2P);
            if (cn < 8)
                cp_async16(&ASF(buf, arow, akq * 4), nf + gArow * HD + kc + akq * 4);
            else
                cp_async8(&ASH(buf, arow, akq * 4), g_hagg_h + gArow * HD + kc + akq * 4);
            cp_async16(&WH2(buf, wkr, wcc * 4),     Whn + (long)(kc + wkr) * 128 + wcc * 4);
            cp_async16(&WH2(buf, wkr + 8, wcc * 4), Whn + (long)(kc + 8 + wkr) * 128 + wcc * 4);
            cp_async16(&WL2(buf, wkr, wcc * 4),     Wln + (long)(kc + wkr) * 128 + wcc * 4);
            cp_async16(&WL2(buf, wkr + 8, wcc * 4), Wln + (long)(kc + 8 + wkr) * 128 + wcc * 4);
        }
        CP_COMMIT();
        CP_WAIT1();
        __syncthreads();
        const int buf = c & 1;
        #pragma unroll
        for (int k8 = 0; k8 < 16; k8 += 8) {
            uint32_t ahi[2][4], alo[2][4], bhi[4][2], blo[4][2];
            #pragma unroll
            for (int mf = 0; mf < 2; mf++) {
                int mb = wm * 32 + mf * 16;
                float a0, a1, a2, a3;
                if (c < 8) {
                    a0 = ASF(buf, mb + g, k8 + tig);
                    a1 = ASF(buf, mb + 8 + g, k8 + tig);
                    a2 = ASF(buf, mb + g, k8 + tig + 4);
                    a3 = ASF(buf, mb + 8 + g, k8 + tig + 4);
                } else {
                    a0 = __half2float(ASH(buf, mb + g, k8 + tig));
                    a1 = __half2float(ASH(buf, mb + 8 + g, k8 + tig));
                    a2 = __half2float(ASH(buf, mb + g, k8 + tig + 4));
                    a3 = __half2float(ASH(buf, mb + 8 + g, k8 + tig + 4));
                }
                float2 s0 = split_f(a0), s1 = split_f(a1);
                float2 s2 = split_f(a2), s3 = split_f(a3);
                ahi[mf][0] = __float_as_uint(s0.x); alo[mf][0] = __float_as_uint(s0.y);
                ahi[mf][1] = __float_as_uint(s1.x); alo[mf][1] = __float_as_uint(s1.y);
                ahi[mf][2] = __float_as_uint(s2.x); alo[mf][2] = __float_as_uint(s2.y);
                ahi[mf][3] = __float_as_uint(s3.x); alo[mf][3] = __float_as_uint(s3.y);
            }
            #pragma unroll
            for (int nf2 = 0; nf2 < 4; nf2++) {
                int nb = wn * 32 + nf2 * 8;
                bhi[nf2][0] = __float_as_uint(WH2(buf, k8 + tig, nb + g));
                bhi[nf2][1] = __float_as_uint(WH2(buf, k8 + tig + 4, nb + g));
                blo[nf2][0] = __float_as_uint(WL2(buf, k8 + tig, nb + g));
                blo[nf2][1] = __float_as_uint(WL2(buf, k8 + tig + 4, nb + g));
            }
            #pragma unroll
            for (int mf = 0; mf < 2; mf++)
                #pragma unroll
                for (int nf2 = 0; nf2 < 4; nf2++) {
                    mma_tf32(d[mf][nf2], ahi[mf], bhi[nf2]);
                    mma_tf32(d[mf][nf2], alo[mf], bhi[nf2]);
                    mma_tf32(d[mf][nf2], ahi[mf], blo[nf2]);
                }
        }
        __syncthreads();
    }

    #pragma unroll
    for (int mf = 0; mf < 2; mf++)
        #pragma unroll
        for (int r2 = 0; r2 < 2; r2++) {
            int lr = wm * 32 + mf * 16 + g + r2 * 8;
            #pragma unroll
            for (int nf2 = 0; nf2 < 4; nf2++) {
                int n = wn * 32 + nf2 * 8 + 2 * tig;
                CS2(lr, n)     = d[mf][nf2][r2 * 2];
                CS2(lr, n + 1) = d[mf][nf2][r2 * 2 + 1];
            }
        }
    __syncthreads();

    #pragma unroll
    for (int r8 = 0; r8 < 8; r8++) {
        int lr = warp * 8 + r8;
        long row = rBase + lr;
        long rowc = row < N_NODES ? row : N_NODES - 1;
        float dg = g_deg[rowc];
        int cc = lane * 4;
        float4 v = *(float4*)&CS2(lr, cc);
        float4 ub = *(const float4*)&ub1[cc];
        float4 dd = *(const float4*)&g_d2[cc];
        v.x += ub.x + dg * dd.x; v.y += ub.y + dg * dd.y;
        v.z += ub.z + dg * dd.z; v.w += ub.w + dg * dd.w;
        float s1 = v.x + v.y + v.z + v.w;
        float ss = v.x * v.x + v.y * v.y + v.z * v.z + v.w * v.w;
        #pragma unroll
        for (int o = 16; o >= 1; o >>= 1) {
            s1 += __shfl_xor_sync(0xffffffffu, s1, o);
            ss += __shfl_xor_sync(0xffffffffu, ss, o);
        }
        float mean = s1 * (1.0f / HD);
        float var  = ss * (1.0f / HD) - mean * mean;
        float rstd = rsqrtf(var + LN_EPS);
        float4 gg = *(const float4*)&g2[cc];
        float4 bb = *(const float4*)&be2[cc];
        float4 h;
        h.x = fmaxf((v.x - mean) * rstd * gg.x + bb.x, 0.f);
        h.y = fmaxf((v.y - mean) * rstd * gg.y + bb.y, 0.f);
        h.z = fmaxf((v.z - mean) * rstd * gg.z + bb.z, 0.f);
        h.w = fmaxf((v.w - mean) * rstd * gg.w + bb.w, 0.f);
        *(float4*)&CS2(lr, cc) = h;
    }
    __syncthreads();

    #pragma unroll
    for (int mf = 0; mf < 2; mf++)
        #pragma unroll
        for (int nf2 = 0; nf2 < 4; nf2++)
            #pragma unroll
            for (int q = 0; q < 4; q++) d[mf][nf2][q] = 0.f;
    {
        const float* Wh0 = g_Whi + OFF_UW2;
        const float* Wl0 = g_Wlo + OFF_UW2;
        cp_async16(&WH2(0, wkr, wcc * 4),     Wh0 + (long)wkr * 128 + wcc * 4);
        cp_async16(&WH2(0, wkr + 8, wcc * 4), Wh0 + (long)(wkr + 8) * 128 + wcc * 4);
        cp_async16(&WL2(0, wkr, wcc * 4),     Wl0 + (long)wkr * 128 + wcc * 4);
        cp_async16(&WL2(0, wkr + 8, wcc * 4), Wl0 + (long)(wkr + 8) * 128 + wcc * 4);
        CP_COMMIT();
    }
    for (int c = 0; c < 8; c++) {
        if (c + 1 < 8) {
            int kc = (c + 1) * 16, buf = (c + 1) & 1;
            const float* Whn = g_Whi + OFF_UW2;
            const float* Wln = g_Wlo + OFF_UW2;
            cp_async16(&WH2(buf, wkr, wcc * 4),     Whn + (long)(kc + wkr) * 128 + wcc * 4);
            cp_async16(&WH2(buf, wkr + 8, wcc * 4), Whn + (long)(kc + 8 + wkr) * 128 + wcc * 4);
            cp_async16(&WL2(buf, wkr, wcc * 4),     Wln + (long)(kc + wkr) * 128 + wcc * 4);
            cp_async16(&WL2(buf, wkr + 8, wcc * 4), Wln + (long)(kc + 8 + wkr) * 128 + wcc * 4);
        }
        CP_COMMIT();
        CP_WAIT1();
        __syncthreads();
        const int buf = c & 1;
        const int kc0 = c * 16;
        #pragma unroll
        for (int k8 = 0; k8 < 16; k8 += 8) {
            uint32_t ahi[2][4], alo[2][4], bhi[4][2], blo[4][2];
            #pragma unroll
            for (int mf = 0; mf < 2; mf++) {
                int mb = wm * 32 + mf * 16;
                float2 s0 = split_f(CS2(mb + g,     kc0 + k8 + tig));
                float2 s1 = split_f(CS2(mb + 8 + g, kc0 + k8 + tig));
                float2 s2 = split_f(CS2(mb + g,     kc0 + k8 + tig + 4));
                float2 s3 = split_f(CS2(mb + 8 + g, kc0 + k8 + tig + 4));
                ahi[mf][0] = __float_as_uint(s0.x); alo[mf][0] = __float_as_uint(s0.y);
                ahi[mf][1] = __float_as_uint(s1.x); alo[mf][1] = __float_as_uint(s1.y);
                ahi[mf][2] = __float_as_uint(s2.x); alo[mf][2] = __float_as_uint(s2.y);
                ahi[mf][3] = __float_as_uint(s3.x); alo[mf][3] = __float_as_uint(s3.y);
            }
            #pragma unroll
            for (int nf2 = 0; nf2 < 4; nf2++) {
                int nb = wn * 32 + nf2 * 8;
                bhi[nf2][0] = __float_as_uint(WH2(buf, k8 + tig, nb + g));
                bhi[nf2][1] = __float_as_uint(WH2(buf, k8 + tig + 4, nb + g));
                blo[nf2][0] = __float_as_uint(WL2(buf, k8 + tig, nb + g));
                blo[nf2][1] = __float_as_uint(WL2(buf, k8 + tig + 4, nb + g));
            }
            #pragma unroll
            for (int mf = 0; mf < 2; mf++)
                #pragma unroll
                for (int nf2 = 0; nf2 < 4; nf2++) {
                    mma_tf32(d[mf][nf2], ahi[mf], bhi[nf2]);
                    mma_tf32(d[mf][nf2], alo[mf], bhi[nf2]);
                    mma_tf32(d[mf][nf2], ahi[mf], blo[nf2]);
                }
        }
        __syncthreads();
    }

    #pragma unroll
    for (int mf = 0; mf < 2; mf++) {
        #pragma unroll
        for (int r2 = 0; r2 < 2; r2++) {
            long m = rBase + wm * 32 + mf * 16 + g + r2 * 8;
            if (m < N_NODES) {
                #pragma unroll
                for (int nf2 = 0; nf2 < 4; nf2++) {
                    int n = wn * 32 + nf2 * 8 + 2 * tig;
                    float2 rr = *(const float2*)(nf + m * 128 + n);
                    float v0 = d[mf][nf2][r2 * 2]     + ub2[n]     + rr.x;
                    float v1 = d[mf][nf2][r2 * 2 + 1] + ub2[n + 1] + rr.y;
                    *(float2*)(out + m * 128 + n) = make_float2(v0, v1);
                }
            }
        }
    }
}

extern "C" void kernel_launch(void* const* d_in, const int* in_sizes, int n_in,
                              void* d_out, int out_size)
{
    const float* nf   = (const float*)d_in[0];
    const float* ef   = (const float*)d_in[1];
    const int*   eidx = (const int*)  d_in[2];
    const float* w1   = (const float*)d_in[3];
    const float* b1   = (const float*)d_in[4];
    const float* g1   = (const float*)d_in[5];
    const float* be1  = (const float*)d_in[6];
    const float* w2   = (const float*)d_in[7];
    const float* b2   = (const float*)d_in[8];
    const float* uw1  = (const float*)d_in[9];
    const float* ub1  = (const float*)d_in[10];
    const float* g2   = (const float*)d_in[11];
    const float* be2  = (const float*)d_in[12];
    const float* uw2  = (const float*)d_in[13];
    const float* ub2  = (const float*)d_in[14];
    float* out = (float*)d_out;

    __half* dPQ;
    cudaGetSymbolAddress((void**)&dPQ, g_PQh);

    const int gN = (N_NODES + 63) / 64;   // 1563
    const int gE = E_EDGES / 64;          // 6250

    const int PQ_SMEM  = 12800 * 4;       // 51200 B
    const int UPD_SMEM = 17152 * 4;       // 68608 B
    cudaFuncSetAttribute(gemm_pq,   cudaFuncAttributeMaxDynamicSharedMemorySize, PQ_SMEM);
    cudaFuncSetAttribute(upd_fused2, cudaFuncAttributeMaxDynamicSharedMemorySize, UPD_SMEM);

    zero_kernel<<<592, 256>>>();
    split_all_kernel<<<(N_SPLIT_IN + 255) / 256, 256>>>(w1, uw1, uw2);
    w2p_kernel<<<129, 128>>>(w2, uw1, b2);
    // P and Q in one fused pass
    gemm_pq<<<gN, 256, PQ_SMEM>>>(nf, dPQ);
    // fused message: R-gemm + gather + LN + fp16 scatter
    msg_fused<<<gE, 256>>>(ef, eidx, b1, g1, be1);
    // fused update: GEMM1 + LN + GEMM2 + residual -> out
    upd_fused2<<<gN, 256, UPD_SMEM>>>(nf, ub1, g2, be2, ub2, out);
}